// round 3
// baseline (speedup 1.0000x reference)
#include <cuda_runtime.h>
#include <cstddef>
#include <math.h>

// Problem constants: N=4, H=W=256, C=8, CK=2, ITER=4, HID=16, C2=64.
#define NROW 1024            // n*256+h rows
#define WFN  129

// ---------------- device scratch (no allocations allowed) ----------------
__device__ float  d_gmat[16777216];             // [row][jk][w]  (4*256 x 64 x 256) 67MB
__device__ float  d_dmat[16777216];             // same layout
__device__ float2 d_filt[129 * 64 * 256];       // [wf][jk][hf]  16.9MB
__device__ float2 d_uf[(size_t)1024 * 129 * 8]; // [row][wf][c]  8.45MB
__device__ float  d_u[(size_t)1024 * 256 * 8];  // iterated field 8.4MB

// ---------------- helpers ----------------
__device__ __forceinline__ float gelu_t(float x) {
    float inner = 0.7978845608028654f * (x + 0.044715f * x * x * x);
    return 0.5f * x * (1.0f + tanhf(inner));
}

// MLP weights packed: w1[32]@0, b1[16]@32, w2[256]@48, b2[16]@304, w3[1024]@320, b3[64]@1344
__device__ __forceinline__ void load_mlp_w(float* dst,
    const float* w1, const float* b1, const float* w2, const float* b2,
    const float* w3, const float* b3, int tid, int nthr) {
    for (int i = tid; i < 32;   i += nthr) dst[i]        = w1[i];
    for (int i = tid; i < 16;   i += nthr) dst[32 + i]   = b1[i];
    for (int i = tid; i < 256;  i += nthr) dst[48 + i]   = w2[i];
    for (int i = tid; i < 16;   i += nthr) dst[304 + i]  = b2[i];
    for (int i = tid; i < 1024; i += nthr) dst[320 + i]  = w3[i];
    for (int i = tid; i < 64;   i += nthr) dst[1344 + i] = b3[i];
}

// 2-input MLP through second gelu layer (16 outputs)
__device__ __forceinline__ void mlp2_h2(const float* __restrict__ Wm, float x0, float x1, float* h2) {
    float h1[16];
#pragma unroll
    for (int o = 0; o < 16; o++)
        h1[o] = gelu_t(fmaf(x0, Wm[o], fmaf(x1, Wm[16 + o], Wm[32 + o])));
#pragma unroll
    for (int o = 0; o < 16; o++) {
        float a = Wm[304 + o];
#pragma unroll
        for (int i = 0; i < 16; i++) a = fmaf(h1[i], Wm[48 + i * 16 + o], a);
        h2[o] = gelu_t(a);
    }
}

// In-smem Stockham radix-2 FFT, length 256, nf independent transforms.
// tw[t] = exp(-2*pi*i*t/256).  sign=+1: forward (numpy), sign=-1: unnormalized inverse.
// Requires blockDim.x == 256 and a __syncthreads() before the call. Result ends in xr/xi.
__device__ __forceinline__ void fft_stages(float* xr, float* xi, float* yr, float* yi,
                                           const float2* __restrict__ tw,
                                           int nf, int tid, float sign) {
    float *ar = xr, *ai = xi, *br = yr, *bi = yi;
#pragma unroll
    for (int s = 0; s < 8; s++) {
        int m = 1 << s;
        for (int t = tid; t < nf * 128; t += 256) {
            int base = (t >> 7) << 8;
            int b = t & 127;
            int twi = b & ~(m - 1);
            float2 w = tw[twi];
            float wr = w.x, wi = sign * w.y;
            float c0r = ar[base + b],       c0i = ai[base + b];
            float c1r = ar[base + b + 128], c1i = ai[base + b + 128];
            int o1 = base + b + twi;
            br[o1] = c0r + c1r;
            bi[o1] = c0i + c1i;
            float dr = c0r - c1r, di = c0i - c1i;
            br[o1 + m] = wr * dr - wi * di;
            bi[o1 + m] = wr * di + wi * dr;
        }
        __syncthreads();
        float* tp;
        tp = ar; ar = br; br = tp;
        tp = ai; ai = bi; bi = tp;
    }
}

__device__ __forceinline__ void fill_tw(float2* tws, int tid, int nthr) {
    for (int t = tid; t < 128; t += nthr) {
        float s, c;
        sincospif((float)t * (1.0f / 128.0f), &s, &c);
        tws[t] = make_float2(c, -s);
    }
}

// ---------------- kernel A: gamma/delta per-pixel 8x8 matrices ----------------
__global__ __launch_bounds__(64) void k_mlp_gd(const float* __restrict__ kin,
    const float* gw1, const float* gb1, const float* gw2, const float* gb2,
    const float* gw3, const float* gb3,
    const float* dw1, const float* db1, const float* dw2, const float* db2,
    const float* dw3, const float* db3) {
    __shared__ float Wg[1408], Wd[1408];
    __shared__ float sg[64 * 65];
    int tid = threadIdx.x;
    load_mlp_w(Wg, gw1, gb1, gw2, gb2, gw3, gb3, tid, 64);
    load_mlp_w(Wd, dw1, db1, dw2, db2, dw3, db3, tid, 64);
    __syncthreads();

    int pix = blockIdx.x * 64 + tid;
    float x0 = kin[pix * 2 + 0];
    float x1 = kin[pix * 2 + 1];
    int row = blockIdx.x >> 2;           // n*256 + h
    int w0  = (blockIdx.x & 3) * 64;

    float h2[16];
    // gamma
    mlp2_h2(Wg, x0, x1, h2);
    for (int jk = 0; jk < 64; jk++) {
        float a = Wg[1344 + jk];
#pragma unroll
        for (int i = 0; i < 16; i++) a = fmaf(h2[i], Wg[320 + i * 64 + jk], a);
        sg[tid * 65 + jk] = a * (1.0f / 64.0f);
    }
    __syncthreads();
    {
        float* gbase = d_gmat + (size_t)row * 64 * 256 + w0;
        for (int jk = 0; jk < 64; jk++) gbase[jk * 256 + tid] = sg[tid * 65 + jk];
    }
    __syncthreads();
    // delta
    mlp2_h2(Wd, x0, x1, h2);
    for (int jk = 0; jk < 64; jk++) {
        float a = Wd[1344 + jk];
#pragma unroll
        for (int i = 0; i < 16; i++) a = fmaf(h2[i], Wd[320 + i * 64 + jk], a);
        sg[tid * 65 + jk] = a * (1.0f / 64.0f);
    }
    __syncthreads();
    {
        float* dbase = d_dmat + (size_t)row * 64 * 256 + w0;
        for (int jk = 0; jk < 64; jk++) dbase[jk * 256 + tid] = sg[tid * 65 + jk];
    }
}

// ---------------- kernel B: spectral filter ----------------
// filt[hf][wf] gets MLP input (kx, ky) = (wf, signed(hf)); stored [wf][jk][hf].
// Scale folds 1/C2 and both inverse-FFT norms: 1/(64*65536).
__global__ __launch_bounds__(256) void k_filt(
    const float* rw1, const float* rb1, const float* rw2, const float* rb2,
    const float* rw3, const float* rb3,
    const float* iw1, const float* ib1, const float* iw2, const float* ib2,
    const float* iw3, const float* ib3) {
    __shared__ float Wr[1408], Wi[1408];
    int tid = threadIdx.x;
    load_mlp_w(Wr, rw1, rb1, rw2, rb2, rw3, rb3, tid, 256);
    load_mlp_w(Wi, iw1, ib1, iw2, ib2, iw3, ib3, tid, 256);
    __syncthreads();

    int wf = blockIdx.x;
    int hf = tid;
    float x0 = (float)wf;
    float x1 = (float)(hf < 128 ? hf : hf - 256);
    float h2r[16], h2i[16];
    mlp2_h2(Wr, x0, x1, h2r);
    mlp2_h2(Wi, x0, x1, h2i);
    const float sc = 1.0f / (64.0f * 65536.0f);
    float2* base = d_filt + (size_t)wf * 64 * 256 + hf;
    for (int jk = 0; jk < 64; jk++) {
        float vr = Wr[1344 + jk], vi = Wi[1344 + jk];
#pragma unroll
        for (int i = 0; i < 16; i++) {
            vr = fmaf(h2r[i], Wr[320 + i * 64 + jk], vr);
            vi = fmaf(h2i[i], Wi[320 + i * 64 + jk], vi);
        }
        base[jk * 256] = make_float2(vr * sc, vi * sc);
    }
}

// ---------------- row pass ----------------
// MODE 0: du = u_in @ D, rfft_W -> Uf
// MODE 1: gu = irfft_W(Uf) ; u' = 2u + (gu-u)@G -> d_u ; du = u'@D ; rfft_W -> Uf
// MODE 2: gu = irfft_W(Uf) ; u' = 2u + (gu-u)@G ; out = gelu(u'+bias)
template <int MODE>
__global__ __launch_bounds__(256) void k_row(const float* __restrict__ uin,
                                             const float* __restrict__ bias,
                                             float* __restrict__ outp) {
    __shared__ float xr[1024], xi[1024], yr[1024], yi[1024];
    __shared__ float2 tws[128];
    __shared__ float2 s_uf[129 * 8];

    int tid = threadIdx.x;
    int row = blockIdx.x;                       // n*256 + h
    fill_tw(tws, tid, 256);

    float2* ufrow = d_uf + (size_t)row * 129 * 8;
    const float* ubase = (uin != nullptr) ? uin : d_u;
    const float* urow  = ubase + (size_t)row * 2048;

    float unew[8];
    int w = tid;

    if (MODE == 0) {
        const float4* up = (const float4*)(urow + w * 8);
        float4 a = up[0], b = up[1];
        unew[0] = a.x; unew[1] = a.y; unew[2] = a.z; unew[3] = a.w;
        unew[4] = b.x; unew[5] = b.y; unew[6] = b.z; unew[7] = b.w;
    } else {
        // load filtered spectrum; drop Im at DC and Nyquist (c2r semantics)
        for (int idx = tid; idx < 1032; idx += 256) {
            float2 v = ufrow[idx];
            int wf = idx >> 3;
            if (wf == 0 || wf == 128) v.y = 0.0f;
            s_uf[idx] = v;
        }
        __syncthreads();
        // build packed inverse input: Z = A + iB with Hermitian extension
        {
            int k = tid;
            int m = (256 - k) & 255;
#pragma unroll
            for (int p = 0; p < 4; p++) {
                if (k <= 128) {
                    float2 A = s_uf[k * 8 + 2 * p];
                    float2 B = s_uf[k * 8 + 2 * p + 1];
                    xr[p * 256 + k] = A.x - B.y;
                    xi[p * 256 + k] = A.y + B.x;
                } else {
                    float2 A = s_uf[m * 8 + 2 * p];
                    float2 B = s_uf[m * 8 + 2 * p + 1];
                    xr[p * 256 + k] = A.x + B.y;
                    xi[p * 256 + k] = B.x - A.y;
                }
            }
        }
        __syncthreads();
        fft_stages(xr, xi, yr, yi, tws, 4, tid, -1.0f);   // inverse (unnormalized)

        float gu[8], uu[8];
#pragma unroll
        for (int p = 0; p < 4; p++) {
            gu[2 * p]     = xr[p * 256 + w];
            gu[2 * p + 1] = xi[p * 256 + w];
        }
        {
            const float4* up = (const float4*)(urow + w * 8);
            float4 a = up[0], b = up[1];
            uu[0] = a.x; uu[1] = a.y; uu[2] = a.z; uu[3] = a.w;
            uu[4] = b.x; uu[5] = b.y; uu[6] = b.z; uu[7] = b.w;
        }
        float tv[8];
#pragma unroll
        for (int j = 0; j < 8; j++) tv[j] = gu[j] - uu[j];
#pragma unroll
        for (int kk = 0; kk < 8; kk++) unew[kk] = 2.0f * uu[kk];
        const float* G = d_gmat + (size_t)row * 64 * 256 + w;
#pragma unroll
        for (int j = 0; j < 8; j++) {
            float tj = tv[j];
#pragma unroll
            for (int kk = 0; kk < 8; kk++)
                unew[kk] = fmaf(tj, G[(j * 8 + kk) * 256], unew[kk]);
        }
        if (MODE == 2) {
            float4 o0, o1;
            o0.x = gelu_t(unew[0] + bias[0]);
            o0.y = gelu_t(unew[1] + bias[1]);
            o0.z = gelu_t(unew[2] + bias[2]);
            o0.w = gelu_t(unew[3] + bias[3]);
            o1.x = gelu_t(unew[4] + bias[4]);
            o1.y = gelu_t(unew[5] + bias[5]);
            o1.z = gelu_t(unew[6] + bias[6]);
            o1.w = gelu_t(unew[7] + bias[7]);
            float4* op = (float4*)(outp + (size_t)row * 2048 + w * 8);
            op[0] = o0; op[1] = o1;
            return;
        }
        // MODE 1: persist u'
        {
            float4 o0, o1;
            o0.x = unew[0]; o0.y = unew[1]; o0.z = unew[2]; o0.w = unew[3];
            o1.x = unew[4]; o1.y = unew[5]; o1.z = unew[6]; o1.w = unew[7];
            float4* op = (float4*)(d_u + (size_t)row * 2048 + w * 8);
            op[0] = o0; op[1] = o1;
        }
    }

    // du = unew @ D ; pack ; forward FFT ; unpack rfft ; write Uf
    {
        const float* D = d_dmat + (size_t)row * 64 * 256 + w;
        float du[8];
#pragma unroll
        for (int kk = 0; kk < 8; kk++) du[kk] = 0.0f;
#pragma unroll
        for (int j = 0; j < 8; j++) {
            float uj = unew[j];
#pragma unroll
            for (int kk = 0; kk < 8; kk++)
                du[kk] = fmaf(uj, D[(j * 8 + kk) * 256], du[kk]);
        }
#pragma unroll
        for (int p = 0; p < 4; p++) {
            xr[p * 256 + w] = du[2 * p];
            xi[p * 256 + w] = du[2 * p + 1];
        }
        __syncthreads();
        fft_stages(xr, xi, yr, yi, tws, 4, tid, 1.0f);    // forward
        if (tid <= 128) {
            int k2 = tid, m2 = (256 - k2) & 255;
#pragma unroll
            for (int p = 0; p < 4; p++) {
                float Zr = xr[p * 256 + k2], Zi = xi[p * 256 + k2];
                float Qr = xr[p * 256 + m2], Qi = xi[p * 256 + m2];
                float2 A = make_float2(0.5f * (Zr + Qr), 0.5f * (Zi - Qi));
                float2 B = make_float2(0.5f * (Zi + Qi), 0.5f * (Qr - Zr));
                ufrow[k2 * 8 + 2 * p]     = A;
                ufrow[k2 * 8 + 2 * p + 1] = B;
            }
        }
    }
}

// ---------------- column pass: FFT_H, filter matvec, IFFT_H (in-place on Uf) ---------
__global__ __launch_bounds__(256) void k_col() {
    __shared__ float xr[2048], xi[2048], yr[2048], yi[2048];
    __shared__ float2 tws[128];
    int tid = threadIdx.x;
    int wf = blockIdx.x % 129;
    int n  = blockIdx.x / 129;
    fill_tw(tws, tid, 256);

    float2* base = d_uf + ((size_t)n * 256 * 129 + wf) * 8;  // + h*129*8 + c
    for (int it = 0; it < 8; it++) {
        int idx = it * 256 + tid;
        int h = idx >> 3, c = idx & 7;
        float2 v = base[(size_t)h * 129 * 8 + c];
        xr[c * 256 + h] = v.x;
        xi[c * 256 + h] = v.y;
    }
    __syncthreads();
    fft_stages(xr, xi, yr, yi, tws, 8, tid, 1.0f);           // forward along H

    int hf = tid;
    float vr[8], vi[8];
#pragma unroll
    for (int kk = 0; kk < 8; kk++) { vr[kk] = 0.0f; vi[kk] = 0.0f; }
    const float2* F = d_filt + (size_t)wf * 64 * 256 + hf;
#pragma unroll
    for (int j = 0; j < 8; j++) {
        float zr = xr[j * 256 + hf], zi = xi[j * 256 + hf];
#pragma unroll
        for (int kk = 0; kk < 8; kk++) {
            float2 f = F[(j * 8 + kk) * 256];
            vr[kk] = fmaf(zr, f.x, fmaf(-zi, f.y, vr[kk]));
            vi[kk] = fmaf(zr, f.y, fmaf(zi, f.x, vi[kk]));
        }
    }
#pragma unroll
    for (int kk = 0; kk < 8; kk++) {
        yr[kk * 256 + hf] = vr[kk];
        yi[kk * 256 + hf] = vi[kk];
    }
    __syncthreads();
    fft_stages(yr, yi, xr, xi, tws, 8, tid, -1.0f);          // inverse (unnormalized)

    for (int it = 0; it < 8; it++) {
        int idx = it * 256 + tid;
        int h = idx >> 3, c = idx & 7;
        base[(size_t)h * 129 * 8 + c] = make_float2(yr[c * 256 + h], yi[c * 256 + h]);
    }
}

// ---------------- launch ----------------
extern "C" void kernel_launch(void* const* d_in, const int* in_sizes, int n_in,
                              void* d_out, int out_size) {
    const float* u    = (const float*)d_in[0];
    const float* kk   = (const float*)d_in[1];
    const float* gW[6];  for (int i = 0; i < 6; i++) gW[i]  = (const float*)d_in[2 + i];
    const float* dW[6];  for (int i = 0; i < 6; i++) dW[i]  = (const float*)d_in[8 + i];
    const float* frW[6]; for (int i = 0; i < 6; i++) frW[i] = (const float*)d_in[14 + i];
    const float* fiW[6]; for (int i = 0; i < 6; i++) fiW[i] = (const float*)d_in[20 + i];
    const float* bias = (const float*)d_in[26];
    float* out = (float*)d_out;

    k_mlp_gd<<<4096, 64>>>(kk,
        gW[0], gW[1], gW[2], gW[3], gW[4], gW[5],
        dW[0], dW[1], dW[2], dW[3], dW[4], dW[5]);
    k_filt<<<129, 256>>>(
        frW[0], frW[1], frW[2], frW[3], frW[4], frW[5],
        fiW[0], fiW[1], fiW[2], fiW[3], fiW[4], fiW[5]);

    k_row<0><<<NROW, 256>>>(u, nullptr, nullptr);
    for (int it = 0; it < 4; it++) {
        k_col<<<4 * 129, 256>>>();
        if (it < 3) {
            k_row<1><<<NROW, 256>>>(it == 0 ? u : nullptr, nullptr, nullptr);
        } else {
            k_row<2><<<NROW, 256>>>(nullptr, bias, out);
        }
    }
}

// round 4
// speedup vs baseline: 1.0001x; 1.0001x over previous
#include <cuda_runtime.h>
#include <cstddef>
#include <math.h>

// Problem constants: N=4, H=W=256, C=8, CK=2, ITER=4, HID=16, C2=64.
#define NROW 1024            // n*256+h rows
#define WFN  129

// ---------------- device scratch (no allocations allowed) ----------------
__device__ float  d_gmat[16777216];             // [row][jk][w]  (4*256 x 64 x 256) 67MB
__device__ float  d_dmat[16777216];             // same layout
__device__ float2 d_filt[129 * 64 * 256];       // [wf][jk][hf]  16.9MB
__device__ float2 d_uf[(size_t)1024 * 129 * 8]; // [row][wf][c]  8.45MB
__device__ float  d_u[(size_t)1024 * 256 * 8];  // iterated field 8.4MB

// ---------------- helpers ----------------
__device__ __forceinline__ float gelu_t(float x) {
    float inner = 0.7978845608028654f * (x + 0.044715f * x * x * x);
    return 0.5f * x * (1.0f + tanhf(inner));
}

// MLP weights packed: w1[32]@0, b1[16]@32, w2[256]@48, b2[16]@304, w3[1024]@320, b3[64]@1344
__device__ __forceinline__ void load_mlp_w(float* dst,
    const float* w1, const float* b1, const float* w2, const float* b2,
    const float* w3, const float* b3, int tid, int nthr) {
    for (int i = tid; i < 32;   i += nthr) dst[i]        = w1[i];
    for (int i = tid; i < 16;   i += nthr) dst[32 + i]   = b1[i];
    for (int i = tid; i < 256;  i += nthr) dst[48 + i]   = w2[i];
    for (int i = tid; i < 16;   i += nthr) dst[304 + i]  = b2[i];
    for (int i = tid; i < 1024; i += nthr) dst[320 + i]  = w3[i];
    for (int i = tid; i < 64;   i += nthr) dst[1344 + i] = b3[i];
}

// 2-input MLP through second gelu layer (16 outputs)
__device__ __forceinline__ void mlp2_h2(const float* __restrict__ Wm, float x0, float x1, float* h2) {
    float h1[16];
#pragma unroll
    for (int o = 0; o < 16; o++)
        h1[o] = gelu_t(fmaf(x0, Wm[o], fmaf(x1, Wm[16 + o], Wm[32 + o])));
#pragma unroll
    for (int o = 0; o < 16; o++) {
        float a = Wm[304 + o];
#pragma unroll
        for (int i = 0; i < 16; i++) a = fmaf(h1[i], Wm[48 + i * 16 + o], a);
        h2[o] = gelu_t(a);
    }
}

// In-smem Stockham radix-2 FFT, length 256, nf independent transforms.
// tw[t] = exp(-2*pi*i*t/256).  sign=+1: forward (numpy), sign=-1: unnormalized inverse.
// Requires blockDim.x == 256 and a __syncthreads() before the call. Result ends in xr/xi.
__device__ __forceinline__ void fft_stages(float* xr, float* xi, float* yr, float* yi,
                                           const float2* __restrict__ tw,
                                           int nf, int tid, float sign) {
    float *ar = xr, *ai = xi, *br = yr, *bi = yi;
#pragma unroll
    for (int s = 0; s < 8; s++) {
        int m = 1 << s;
        for (int t = tid; t < nf * 128; t += 256) {
            int base = (t >> 7) << 8;
            int b = t & 127;
            int twi = b & ~(m - 1);
            float2 w = tw[twi];
            float wr = w.x, wi = sign * w.y;
            float c0r = ar[base + b],       c0i = ai[base + b];
            float c1r = ar[base + b + 128], c1i = ai[base + b + 128];
            int o1 = base + b + twi;
            br[o1] = c0r + c1r;
            bi[o1] = c0i + c1i;
            float dr = c0r - c1r, di = c0i - c1i;
            br[o1 + m] = wr * dr - wi * di;
            bi[o1 + m] = wr * di + wi * dr;
        }
        __syncthreads();
        float* tp;
        tp = ar; ar = br; br = tp;
        tp = ai; ai = bi; bi = tp;
    }
}

__device__ __forceinline__ void fill_tw(float2* tws, int tid, int nthr) {
    for (int t = tid; t < 128; t += nthr) {
        float s, c;
        sincospif((float)t * (1.0f / 128.0f), &s, &c);
        tws[t] = make_float2(c, -s);
    }
}

// ---------------- kernel A: gamma/delta per-pixel 8x8 matrices ----------------
__global__ __launch_bounds__(64) void k_mlp_gd(const float* __restrict__ kin,
    const float* gw1, const float* gb1, const float* gw2, const float* gb2,
    const float* gw3, const float* gb3,
    const float* dw1, const float* db1, const float* dw2, const float* db2,
    const float* dw3, const float* db3) {
    __shared__ float Wg[1408], Wd[1408];
    __shared__ float sg[64 * 65];
    int tid = threadIdx.x;
    load_mlp_w(Wg, gw1, gb1, gw2, gb2, gw3, gb3, tid, 64);
    load_mlp_w(Wd, dw1, db1, dw2, db2, dw3, db3, tid, 64);
    __syncthreads();

    int pix = blockIdx.x * 64 + tid;
    float x0 = kin[pix * 2 + 0];
    float x1 = kin[pix * 2 + 1];
    int row = blockIdx.x >> 2;           // n*256 + h
    int w0  = (blockIdx.x & 3) * 64;

    float h2[16];
    // gamma
    mlp2_h2(Wg, x0, x1, h2);
    for (int jk = 0; jk < 64; jk++) {
        float a = Wg[1344 + jk];
#pragma unroll
        for (int i = 0; i < 16; i++) a = fmaf(h2[i], Wg[320 + i * 64 + jk], a);
        sg[tid * 65 + jk] = a * (1.0f / 64.0f);
    }
    __syncthreads();
    {
        float* gbase = d_gmat + (size_t)row * 64 * 256 + w0;
        for (int jk = 0; jk < 64; jk++) gbase[jk * 256 + tid] = sg[tid * 65 + jk];
    }
    __syncthreads();
    // delta
    mlp2_h2(Wd, x0, x1, h2);
    for (int jk = 0; jk < 64; jk++) {
        float a = Wd[1344 + jk];
#pragma unroll
        for (int i = 0; i < 16; i++) a = fmaf(h2[i], Wd[320 + i * 64 + jk], a);
        sg[tid * 65 + jk] = a * (1.0f / 64.0f);
    }
    __syncthreads();
    {
        float* dbase = d_dmat + (size_t)row * 64 * 256 + w0;
        for (int jk = 0; jk < 64; jk++) dbase[jk * 256 + tid] = sg[tid * 65 + jk];
    }
}

// ---------------- kernel B: spectral filter ----------------
// filt[hf][wf] gets MLP input (kx, ky) = (wf, signed(hf)); stored [wf][jk][hf].
// Scale folds 1/C2 and both inverse-FFT norms: 1/(64*65536).
__global__ __launch_bounds__(256) void k_filt(
    const float* rw1, const float* rb1, const float* rw2, const float* rb2,
    const float* rw3, const float* rb3,
    const float* iw1, const float* ib1, const float* iw2, const float* ib2,
    const float* iw3, const float* ib3) {
    __shared__ float Wr[1408], Wi[1408];
    int tid = threadIdx.x;
    load_mlp_w(Wr, rw1, rb1, rw2, rb2, rw3, rb3, tid, 256);
    load_mlp_w(Wi, iw1, ib1, iw2, ib2, iw3, ib3, tid, 256);
    __syncthreads();

    int wf = blockIdx.x;
    int hf = tid;
    float x0 = (float)wf;
    float x1 = (float)(hf < 128 ? hf : hf - 256);
    float h2r[16], h2i[16];
    mlp2_h2(Wr, x0, x1, h2r);
    mlp2_h2(Wi, x0, x1, h2i);
    const float sc = 1.0f / (64.0f * 65536.0f);
    float2* base = d_filt + (size_t)wf * 64 * 256 + hf;
    for (int jk = 0; jk < 64; jk++) {
        float vr = Wr[1344 + jk], vi = Wi[1344 + jk];
#pragma unroll
        for (int i = 0; i < 16; i++) {
            vr = fmaf(h2r[i], Wr[320 + i * 64 + jk], vr);
            vi = fmaf(h2i[i], Wi[320 + i * 64 + jk], vi);
        }
        base[jk * 256] = make_float2(vr * sc, vi * sc);
    }
}

// ---------------- row pass ----------------
// MODE 0: du = u_in @ D, rfft_W -> Uf
// MODE 1: gu = irfft_W(Uf) ; u' = 2u + (gu-u)@G -> d_u ; du = u'@D ; rfft_W -> Uf
// MODE 2: gu = irfft_W(Uf) ; u' = 2u + (gu-u)@G ; out = gelu(u'+bias)
template <int MODE>
__global__ __launch_bounds__(256) void k_row(const float* __restrict__ uin,
                                             const float* __restrict__ bias,
                                             float* __restrict__ outp) {
    __shared__ float xr[1024], xi[1024], yr[1024], yi[1024];
    __shared__ float2 tws[128];
    __shared__ float2 s_uf[129 * 8];

    int tid = threadIdx.x;
    int row = blockIdx.x;                       // n*256 + h
    fill_tw(tws, tid, 256);

    float2* ufrow = d_uf + (size_t)row * 129 * 8;
    const float* ubase = (uin != nullptr) ? uin : d_u;
    const float* urow  = ubase + (size_t)row * 2048;

    float unew[8];
    int w = tid;

    if (MODE == 0) {
        const float4* up = (const float4*)(urow + w * 8);
        float4 a = up[0], b = up[1];
        unew[0] = a.x; unew[1] = a.y; unew[2] = a.z; unew[3] = a.w;
        unew[4] = b.x; unew[5] = b.y; unew[6] = b.z; unew[7] = b.w;
    } else {
        // load filtered spectrum; drop Im at DC and Nyquist (c2r semantics)
        for (int idx = tid; idx < 1032; idx += 256) {
            float2 v = ufrow[idx];
            int wf = idx >> 3;
            if (wf == 0 || wf == 128) v.y = 0.0f;
            s_uf[idx] = v;
        }
        __syncthreads();
        // build packed inverse input: Z = A + iB with Hermitian extension
        {
            int k = tid;
            int m = (256 - k) & 255;
#pragma unroll
            for (int p = 0; p < 4; p++) {
                if (k <= 128) {
                    float2 A = s_uf[k * 8 + 2 * p];
                    float2 B = s_uf[k * 8 + 2 * p + 1];
                    xr[p * 256 + k] = A.x - B.y;
                    xi[p * 256 + k] = A.y + B.x;
                } else {
                    float2 A = s_uf[m * 8 + 2 * p];
                    float2 B = s_uf[m * 8 + 2 * p + 1];
                    xr[p * 256 + k] = A.x + B.y;
                    xi[p * 256 + k] = B.x - A.y;
                }
            }
        }
        __syncthreads();
        fft_stages(xr, xi, yr, yi, tws, 4, tid, -1.0f);   // inverse (unnormalized)

        float gu[8], uu[8];
#pragma unroll
        for (int p = 0; p < 4; p++) {
            gu[2 * p]     = xr[p * 256 + w];
            gu[2 * p + 1] = xi[p * 256 + w];
        }
        {
            const float4* up = (const float4*)(urow + w * 8);
            float4 a = up[0], b = up[1];
            uu[0] = a.x; uu[1] = a.y; uu[2] = a.z; uu[3] = a.w;
            uu[4] = b.x; uu[5] = b.y; uu[6] = b.z; uu[7] = b.w;
        }
        float tv[8];
#pragma unroll
        for (int j = 0; j < 8; j++) tv[j] = gu[j] - uu[j];
#pragma unroll
        for (int kk = 0; kk < 8; kk++) unew[kk] = 2.0f * uu[kk];
        const float* G = d_gmat + (size_t)row * 64 * 256 + w;
#pragma unroll
        for (int j = 0; j < 8; j++) {
            float tj = tv[j];
#pragma unroll
            for (int kk = 0; kk < 8; kk++)
                unew[kk] = fmaf(tj, G[(j * 8 + kk) * 256], unew[kk]);
        }
        if (MODE == 2) {
            float4 o0, o1;
            o0.x = gelu_t(unew[0] + bias[0]);
            o0.y = gelu_t(unew[1] + bias[1]);
            o0.z = gelu_t(unew[2] + bias[2]);
            o0.w = gelu_t(unew[3] + bias[3]);
            o1.x = gelu_t(unew[4] + bias[4]);
            o1.y = gelu_t(unew[5] + bias[5]);
            o1.z = gelu_t(unew[6] + bias[6]);
            o1.w = gelu_t(unew[7] + bias[7]);
            float4* op = (float4*)(outp + (size_t)row * 2048 + w * 8);
            op[0] = o0; op[1] = o1;
            return;
        }
        // MODE 1: persist u'
        {
            float4 o0, o1;
            o0.x = unew[0]; o0.y = unew[1]; o0.z = unew[2]; o0.w = unew[3];
            o1.x = unew[4]; o1.y = unew[5]; o1.z = unew[6]; o1.w = unew[7];
            float4* op = (float4*)(d_u + (size_t)row * 2048 + w * 8);
            op[0] = o0; op[1] = o1;
        }
    }

    // du = unew @ D ; pack ; forward FFT ; unpack rfft ; write Uf
    {
        const float* D = d_dmat + (size_t)row * 64 * 256 + w;
        float du[8];
#pragma unroll
        for (int kk = 0; kk < 8; kk++) du[kk] = 0.0f;
#pragma unroll
        for (int j = 0; j < 8; j++) {
            float uj = unew[j];
#pragma unroll
            for (int kk = 0; kk < 8; kk++)
                du[kk] = fmaf(uj, D[(j * 8 + kk) * 256], du[kk]);
        }
#pragma unroll
        for (int p = 0; p < 4; p++) {
            xr[p * 256 + w] = du[2 * p];
            xi[p * 256 + w] = du[2 * p + 1];
        }
        __syncthreads();
        fft_stages(xr, xi, yr, yi, tws, 4, tid, 1.0f);    // forward
        if (tid <= 128) {
            int k2 = tid, m2 = (256 - k2) & 255;
#pragma unroll
            for (int p = 0; p < 4; p++) {
                float Zr = xr[p * 256 + k2], Zi = xi[p * 256 + k2];
                float Qr = xr[p * 256 + m2], Qi = xi[p * 256 + m2];
                float2 A = make_float2(0.5f * (Zr + Qr), 0.5f * (Zi - Qi));
                float2 B = make_float2(0.5f * (Zi + Qi), 0.5f * (Qr - Zr));
                ufrow[k2 * 8 + 2 * p]     = A;
                ufrow[k2 * 8 + 2 * p + 1] = B;
            }
        }
    }
}

// ---------------- column pass: FFT_H, filter matvec, IFFT_H (in-place on Uf) ---------
__global__ __launch_bounds__(256) void k_col() {
    __shared__ float xr[2048], xi[2048], yr[2048], yi[2048];
    __shared__ float2 tws[128];
    int tid = threadIdx.x;
    int wf = blockIdx.x % 129;
    int n  = blockIdx.x / 129;
    fill_tw(tws, tid, 256);

    float2* base = d_uf + ((size_t)n * 256 * 129 + wf) * 8;  // + h*129*8 + c
    for (int it = 0; it < 8; it++) {
        int idx = it * 256 + tid;
        int h = idx >> 3, c = idx & 7;
        float2 v = base[(size_t)h * 129 * 8 + c];
        xr[c * 256 + h] = v.x;
        xi[c * 256 + h] = v.y;
    }
    __syncthreads();
    fft_stages(xr, xi, yr, yi, tws, 8, tid, 1.0f);           // forward along H

    int hf = tid;
    float vr[8], vi[8];
#pragma unroll
    for (int kk = 0; kk < 8; kk++) { vr[kk] = 0.0f; vi[kk] = 0.0f; }
    const float2* F = d_filt + (size_t)wf * 64 * 256 + hf;
#pragma unroll
    for (int j = 0; j < 8; j++) {
        float zr = xr[j * 256 + hf], zi = xi[j * 256 + hf];
#pragma unroll
        for (int kk = 0; kk < 8; kk++) {
            float2 f = F[(j * 8 + kk) * 256];
            vr[kk] = fmaf(zr, f.x, fmaf(-zi, f.y, vr[kk]));
            vi[kk] = fmaf(zr, f.y, fmaf(zi, f.x, vi[kk]));
        }
    }
#pragma unroll
    for (int kk = 0; kk < 8; kk++) {
        yr[kk * 256 + hf] = vr[kk];
        yi[kk * 256 + hf] = vi[kk];
    }
    __syncthreads();
    fft_stages(yr, yi, xr, xi, tws, 8, tid, -1.0f);          // inverse (unnormalized)

    for (int it = 0; it < 8; it++) {
        int idx = it * 256 + tid;
        int h = idx >> 3, c = idx & 7;
        base[(size_t)h * 129 * 8 + c] = make_float2(yr[c * 256 + h], yi[c * 256 + h]);
    }
}

// ---------------- launch ----------------
extern "C" void kernel_launch(void* const* d_in, const int* in_sizes, int n_in,
                              void* d_out, int out_size) {
    const float* u    = (const float*)d_in[0];
    const float* kk   = (const float*)d_in[1];
    const float* gW[6];  for (int i = 0; i < 6; i++) gW[i]  = (const float*)d_in[2 + i];
    const float* dW[6];  for (int i = 0; i < 6; i++) dW[i]  = (const float*)d_in[8 + i];
    const float* frW[6]; for (int i = 0; i < 6; i++) frW[i] = (const float*)d_in[14 + i];
    const float* fiW[6]; for (int i = 0; i < 6; i++) fiW[i] = (const float*)d_in[20 + i];
    const float* bias = (const float*)d_in[26];
    float* out = (float*)d_out;

    k_mlp_gd<<<4096, 64>>>(kk,
        gW[0], gW[1], gW[2], gW[3], gW[4], gW[5],
        dW[0], dW[1], dW[2], dW[3], dW[4], dW[5]);
    k_filt<<<129, 256>>>(
        frW[0], frW[1], frW[2], frW[3], frW[4], frW[5],
        fiW[0], fiW[1], fiW[2], fiW[3], fiW[4], fiW[5]);

    k_row<0><<<NROW, 256>>>(u, nullptr, nullptr);
    for (int it = 0; it < 4; it++) {
        k_col<<<4 * 129, 256>>>();
        if (it < 3) {
            k_row<1><<<NROW, 256>>>(it == 0 ? u : nullptr, nullptr, nullptr);
        } else {
            k_row<2><<<NROW, 256>>>(nullptr, bias, out);
        }
    }
}

// round 5
// speedup vs baseline: 1.4055x; 1.4054x over previous
#include <cuda_runtime.h>
#include <cuda_fp16.h>
#include <cstddef>
#include <math.h>

// Problem constants: N=4, H=W=256, C=8, CK=2, ITER=4, HID=16, C2=64.
#define NROW 1024            // n*256+h rows

// ---------------- device scratch (no allocations allowed) ----------------
__device__ __half2 d_gmat[8388608];             // [row][jk/2][w]  (1024 x 32 x 256) 33.5MB
__device__ __half2 d_dmat[8388608];             // same layout
__device__ __half2 d_filt[129 * 64 * 256];      // [wf][jk][hf] (re,im) 8.45MB
__device__ float2 d_uf[(size_t)1024 * 129 * 8]; // [row][wf][c]  8.45MB
__device__ float  d_u[(size_t)1024 * 256 * 8];  // iterated field 8.4MB

// ---------------- helpers ----------------
__device__ __forceinline__ float gelu_t(float x) {
    float inner = 0.7978845608028654f * (x + 0.044715f * x * x * x);
    return 0.5f * x * (1.0f + tanhf(inner));
}

// MLP weights packed: w1[32]@0, b1[16]@32, w2[256]@48, b2[16]@304, w3[1024]@320, b3[64]@1344
__device__ __forceinline__ void load_mlp_w(float* dst,
    const float* w1, const float* b1, const float* w2, const float* b2,
    const float* w3, const float* b3, int tid, int nthr) {
    for (int i = tid; i < 32;   i += nthr) dst[i]        = w1[i];
    for (int i = tid; i < 16;   i += nthr) dst[32 + i]   = b1[i];
    for (int i = tid; i < 256;  i += nthr) dst[48 + i]   = w2[i];
    for (int i = tid; i < 16;   i += nthr) dst[304 + i]  = b2[i];
    for (int i = tid; i < 1024; i += nthr) dst[320 + i]  = w3[i];
    for (int i = tid; i < 64;   i += nthr) dst[1344 + i] = b3[i];
}

// 2-input MLP through second gelu layer (16 outputs)
__device__ __forceinline__ void mlp2_h2(const float* __restrict__ Wm, float x0, float x1, float* h2) {
    float h1[16];
#pragma unroll
    for (int o = 0; o < 16; o++)
        h1[o] = gelu_t(fmaf(x0, Wm[o], fmaf(x1, Wm[16 + o], Wm[32 + o])));
#pragma unroll
    for (int o = 0; o < 16; o++) {
        float a = Wm[304 + o];
#pragma unroll
        for (int i = 0; i < 16; i++) a = fmaf(h1[i], Wm[48 + i * 16 + o], a);
        h2[o] = gelu_t(a);
    }
}

// In-smem Stockham radix-4 FFT, length 256, nf independent transforms.
// Exact composition of two radix-2 stages (m, 2m); stages m = 1,4,16,64.
// tw[t] = exp(-2*pi*i*t/256). sign=+1: forward (numpy), sign=-1: unnormalized inverse.
// blockDim.x must be 256; caller syncs before. Result ends in xr/xi (4 swaps).
__device__ __forceinline__ void fft4_stages(float* xr, float* xi, float* yr, float* yi,
                                            const float2* __restrict__ tw,
                                            int nf, int tid, float sign) {
    float *ar = xr, *ai = xi, *br = yr, *bi = yi;
#pragma unroll
    for (int s = 0; s < 4; s++) {
        int m = 1 << (2 * s);            // 1,4,16,64
        for (int t0 = tid; t0 < nf * 64; t0 += 256) {
            int base = (t0 >> 6) << 8;   // transform base
            int t = t0 & 63;
            int jm = t & ~(m - 1);
            int r  = t & (m - 1);
            float2 w1v = tw[jm];
            float2 w2v = tw[2 * jm];
            float w1r = w1v.x, w1i = sign * w1v.y;
            float w2r = w2v.x, w2i = sign * w2v.y;

            float Ar = ar[base + t],       Ai = ai[base + t];
            float Br = ar[base + t + 64],  Bi = ai[base + t + 64];
            float Cr = ar[base + t + 128], Ci = ai[base + t + 128];
            float Dr = ar[base + t + 192], Di = ai[base + t + 192];

            float s0r = Ar + Cr, s0i = Ai + Ci;
            float d0r = Ar - Cr, d0i = Ai - Ci;
            float s2r = Br + Dr, s2i = Bi + Di;
            float d1r = Br - Dr, d1i = Bi - Di;
            // s1 = w1*(A-C)
            float s1r = w1r * d0r - w1i * d0i;
            float s1i = w1r * d0i + w1i * d0r;
            // s3 = w1 * ((-sign*i)*(B-D)):  e = (re: sign*d1i, im: -sign*d1r)
            float er = sign * d1i, ei = -sign * d1r;
            float s3r = w1r * er - w1i * ei;
            float s3i = w1r * ei + w1i * er;

            int o = base + 4 * jm + r;
            br[o]     = s0r + s2r;  bi[o]     = s0i + s2i;
            br[o + m] = s1r + s3r;  bi[o + m] = s1i + s3i;
            float u0r = s0r - s2r, u0i = s0i - s2i;
            br[o + 2 * m] = w2r * u0r - w2i * u0i;
            bi[o + 2 * m] = w2r * u0i + w2i * u0r;
            float u1r = s1r - s3r, u1i = s1i - s3i;
            br[o + 3 * m] = w2r * u1r - w2i * u1i;
            bi[o + 3 * m] = w2r * u1i + w2i * u1r;
        }
        __syncthreads();
        float* tp;
        tp = ar; ar = br; br = tp;
        tp = ai; ai = bi; bi = tp;
    }
}

__device__ __forceinline__ void fill_tw(float2* tws, int tid, int nthr) {
    for (int t = tid; t < 128; t += nthr) {
        float s, c;
        sincospif((float)t * (1.0f / 128.0f), &s, &c);
        tws[t] = make_float2(c, -s);
    }
}

// ---------------- kernel A: gamma/delta per-pixel 8x8 matrices (fp16 out) --------
__global__ __launch_bounds__(64) void k_mlp_gd(const float* __restrict__ kin,
    const float* gw1, const float* gb1, const float* gw2, const float* gb2,
    const float* gw3, const float* gb3,
    const float* dw1, const float* db1, const float* dw2, const float* db2,
    const float* dw3, const float* db3) {
    __shared__ float Wg[1408], Wd[1408];
    __shared__ float sg[64 * 65];
    int tid = threadIdx.x;
    load_mlp_w(Wg, gw1, gb1, gw2, gb2, gw3, gb3, tid, 64);
    load_mlp_w(Wd, dw1, db1, dw2, db2, dw3, db3, tid, 64);
    __syncthreads();

    int pix = blockIdx.x * 64 + tid;
    float x0 = kin[pix * 2 + 0];
    float x1 = kin[pix * 2 + 1];
    int row = blockIdx.x >> 2;           // n*256 + h
    int w   = (blockIdx.x & 3) * 64 + tid;

    float h2[16];
    // gamma
    mlp2_h2(Wg, x0, x1, h2);
    for (int jk = 0; jk < 64; jk++) {
        float a = Wg[1344 + jk];
#pragma unroll
        for (int i = 0; i < 16; i++) a = fmaf(h2[i], Wg[320 + i * 64 + jk], a);
        sg[tid * 65 + jk] = a * (1.0f / 64.0f);
    }
    __syncthreads();
    {
        __half2* gbase = d_gmat + (size_t)row * 32 * 256;
        for (int p = 0; p < 32; p++)
            gbase[p * 256 + w] = __floats2half2_rn(sg[tid * 65 + 2 * p], sg[tid * 65 + 2 * p + 1]);
    }
    __syncthreads();
    // delta
    mlp2_h2(Wd, x0, x1, h2);
    for (int jk = 0; jk < 64; jk++) {
        float a = Wd[1344 + jk];
#pragma unroll
        for (int i = 0; i < 16; i++) a = fmaf(h2[i], Wd[320 + i * 64 + jk], a);
        sg[tid * 65 + jk] = a * (1.0f / 64.0f);
    }
    __syncthreads();
    {
        __half2* dbase = d_dmat + (size_t)row * 32 * 256;
        for (int p = 0; p < 32; p++)
            dbase[p * 256 + w] = __floats2half2_rn(sg[tid * 65 + 2 * p], sg[tid * 65 + 2 * p + 1]);
    }
}

// ---------------- kernel B: spectral filter (fp16 re,im) ----------------
// MLP input (kx, ky) = (wf, signed(hf)); stored [wf][jk][hf]. Scale = 1/64 only;
// the 1/65536 FFT normalization is applied in k_col's store (fp16 would underflow).
__global__ __launch_bounds__(256) void k_filt(
    const float* rw1, const float* rb1, const float* rw2, const float* rb2,
    const float* rw3, const float* rb3,
    const float* iw1, const float* ib1, const float* iw2, const float* ib2,
    const float* iw3, const float* ib3) {
    __shared__ float Wr[1408], Wi[1408];
    int tid = threadIdx.x;
    load_mlp_w(Wr, rw1, rb1, rw2, rb2, rw3, rb3, tid, 256);
    load_mlp_w(Wi, iw1, ib1, iw2, ib2, iw3, ib3, tid, 256);
    __syncthreads();

    int wf = blockIdx.x;
    int hf = tid;
    float x0 = (float)wf;
    float x1 = (float)(hf < 128 ? hf : hf - 256);
    float h2r[16], h2i[16];
    mlp2_h2(Wr, x0, x1, h2r);
    mlp2_h2(Wi, x0, x1, h2i);
    const float sc = 1.0f / 64.0f;
    __half2* base = d_filt + (size_t)wf * 64 * 256 + hf;
    for (int jk = 0; jk < 64; jk++) {
        float vr = Wr[1344 + jk], vi = Wi[1344 + jk];
#pragma unroll
        for (int i = 0; i < 16; i++) {
            vr = fmaf(h2r[i], Wr[320 + i * 64 + jk], vr);
            vi = fmaf(h2i[i], Wi[320 + i * 64 + jk], vi);
        }
        base[jk * 256] = __floats2half2_rn(vr * sc, vi * sc);
    }
}

// ---------------- row pass ----------------
// MODE 0: du = u_in @ D, rfft_W -> Uf
// MODE 1: gu = irfft_W(Uf) ; u' = 2u + (gu-u)@G -> d_u ; du = u'@D ; rfft_W -> Uf
// MODE 2: gu = irfft_W(Uf) ; u' = 2u + (gu-u)@G ; out = gelu(u'+bias)
template <int MODE>
__global__ __launch_bounds__(256) void k_row(const float* __restrict__ uin,
                                             const float* __restrict__ bias,
                                             float* __restrict__ outp) {
    __shared__ float xr[1024], xi[1024], yr[1024], yi[1024];
    __shared__ float2 tws[128];
    __shared__ float2 s_uf[129 * 8];

    int tid = threadIdx.x;
    int row = blockIdx.x;                       // n*256 + h
    fill_tw(tws, tid, 256);

    float2* ufrow = d_uf + (size_t)row * 129 * 8;
    const float* ubase = (uin != nullptr) ? uin : d_u;
    const float* urow  = ubase + (size_t)row * 2048;

    float unew[8];
    int w = tid;

    if (MODE == 0) {
        const float4* up = (const float4*)(urow + w * 8);
        float4 a = up[0], b = up[1];
        unew[0] = a.x; unew[1] = a.y; unew[2] = a.z; unew[3] = a.w;
        unew[4] = b.x; unew[5] = b.y; unew[6] = b.z; unew[7] = b.w;
    } else {
        // load filtered spectrum; drop Im at DC and Nyquist (c2r semantics)
        for (int idx = tid; idx < 1032; idx += 256) {
            float2 v = ufrow[idx];
            int wf = idx >> 3;
            if (wf == 0 || wf == 128) v.y = 0.0f;
            s_uf[idx] = v;
        }
        __syncthreads();
        // packed inverse input: Z = A + iB with Hermitian extension
        {
            int k = tid;
            int m = (256 - k) & 255;
#pragma unroll
            for (int p = 0; p < 4; p++) {
                if (k <= 128) {
                    float2 A = s_uf[k * 8 + 2 * p];
                    float2 B = s_uf[k * 8 + 2 * p + 1];
                    xr[p * 256 + k] = A.x - B.y;
                    xi[p * 256 + k] = A.y + B.x;
                } else {
                    float2 A = s_uf[m * 8 + 2 * p];
                    float2 B = s_uf[m * 8 + 2 * p + 1];
                    xr[p * 256 + k] = A.x + B.y;
                    xi[p * 256 + k] = B.x - A.y;
                }
            }
        }
        __syncthreads();
        fft4_stages(xr, xi, yr, yi, tws, 4, tid, -1.0f);   // inverse (unnormalized)

        float gu[8], uu[8];
#pragma unroll
        for (int p = 0; p < 4; p++) {
            gu[2 * p]     = xr[p * 256 + w];
            gu[2 * p + 1] = xi[p * 256 + w];
        }
        {
            const float4* up = (const float4*)(urow + w * 8);
            float4 a = up[0], b = up[1];
            uu[0] = a.x; uu[1] = a.y; uu[2] = a.z; uu[3] = a.w;
            uu[4] = b.x; uu[5] = b.y; uu[6] = b.z; uu[7] = b.w;
        }
        float tv[8];
#pragma unroll
        for (int j = 0; j < 8; j++) tv[j] = gu[j] - uu[j];
#pragma unroll
        for (int kk = 0; kk < 8; kk++) unew[kk] = 2.0f * uu[kk];
        const __half2* G = d_gmat + (size_t)row * 32 * 256 + w;
#pragma unroll
        for (int j = 0; j < 8; j++) {
            float tj = tv[j];
#pragma unroll
            for (int p = 0; p < 4; p++) {
                float2 g = __half22float2(G[(j * 4 + p) * 256]);
                unew[2 * p]     = fmaf(tj, g.x, unew[2 * p]);
                unew[2 * p + 1] = fmaf(tj, g.y, unew[2 * p + 1]);
            }
        }
        if (MODE == 2) {
            float4 o0, o1;
            o0.x = gelu_t(unew[0] + bias[0]);
            o0.y = gelu_t(unew[1] + bias[1]);
            o0.z = gelu_t(unew[2] + bias[2]);
            o0.w = gelu_t(unew[3] + bias[3]);
            o1.x = gelu_t(unew[4] + bias[4]);
            o1.y = gelu_t(unew[5] + bias[5]);
            o1.z = gelu_t(unew[6] + bias[6]);
            o1.w = gelu_t(unew[7] + bias[7]);
            float4* op = (float4*)(outp + (size_t)row * 2048 + w * 8);
            op[0] = o0; op[1] = o1;
            return;
        }
        // MODE 1: persist u'
        {
            float4 o0, o1;
            o0.x = unew[0]; o0.y = unew[1]; o0.z = unew[2]; o0.w = unew[3];
            o1.x = unew[4]; o1.y = unew[5]; o1.z = unew[6]; o1.w = unew[7];
            float4* op = (float4*)(d_u + (size_t)row * 2048 + w * 8);
            op[0] = o0; op[1] = o1;
        }
    }

    // du = unew @ D ; pack ; forward FFT ; unpack rfft ; write Uf
    {
        const __half2* D = d_dmat + (size_t)row * 32 * 256 + w;
        float du[8];
#pragma unroll
        for (int kk = 0; kk < 8; kk++) du[kk] = 0.0f;
#pragma unroll
        for (int j = 0; j < 8; j++) {
            float uj = unew[j];
#pragma unroll
            for (int p = 0; p < 4; p++) {
                float2 dv = __half22float2(D[(j * 4 + p) * 256]);
                du[2 * p]     = fmaf(uj, dv.x, du[2 * p]);
                du[2 * p + 1] = fmaf(uj, dv.y, du[2 * p + 1]);
            }
        }
        if (MODE != 0) __syncthreads();   // xr/xi still being read above? (gu read done; safe barrier)
#pragma unroll
        for (int p = 0; p < 4; p++) {
            xr[p * 256 + w] = du[2 * p];
            xi[p * 256 + w] = du[2 * p + 1];
        }
        __syncthreads();
        fft4_stages(xr, xi, yr, yi, tws, 4, tid, 1.0f);    // forward
        if (tid <= 128) {
            int k2 = tid, m2 = (256 - k2) & 255;
#pragma unroll
            for (int p = 0; p < 4; p++) {
                float Zr = xr[p * 256 + k2], Zi = xi[p * 256 + k2];
                float Qr = xr[p * 256 + m2], Qi = xi[p * 256 + m2];
                float2 A = make_float2(0.5f * (Zr + Qr), 0.5f * (Zi - Qi));
                float2 B = make_float2(0.5f * (Zi + Qi), 0.5f * (Qr - Zr));
                ufrow[k2 * 8 + 2 * p]     = A;
                ufrow[k2 * 8 + 2 * p + 1] = B;
            }
        }
    }
}

// ---------------- column pass: FFT_H, filter matvec, IFFT_H (in-place on Uf) ---------
__global__ __launch_bounds__(256) void k_col() {
    __shared__ float xr[2048], xi[2048], yr[2048], yi[2048];
    __shared__ float2 tws[128];
    int tid = threadIdx.x;
    int wf = blockIdx.x % 129;
    int n  = blockIdx.x / 129;
    fill_tw(tws, tid, 256);

    float2* base = d_uf + ((size_t)n * 256 * 129 + wf) * 8;  // + h*129*8 + c
    for (int it = 0; it < 8; it++) {
        int idx = it * 256 + tid;
        int h = idx >> 3, c = idx & 7;
        float2 v = base[(size_t)h * 129 * 8 + c];
        xr[c * 256 + h] = v.x;
        xi[c * 256 + h] = v.y;
    }
    __syncthreads();
    fft4_stages(xr, xi, yr, yi, tws, 8, tid, 1.0f);          // forward along H

    int hf = tid;
    float vr[8], vi[8];
#pragma unroll
    for (int kk = 0; kk < 8; kk++) { vr[kk] = 0.0f; vi[kk] = 0.0f; }
    const __half2* F = d_filt + (size_t)wf * 64 * 256 + hf;
#pragma unroll
    for (int j = 0; j < 8; j++) {
        float zr = xr[j * 256 + hf], zi = xi[j * 256 + hf];
#pragma unroll
        for (int kk = 0; kk < 8; kk++) {
            float2 f = __half22float2(F[(j * 8 + kk) * 256]);
            vr[kk] = fmaf(zr, f.x, fmaf(-zi, f.y, vr[kk]));
            vi[kk] = fmaf(zr, f.y, fmaf(zi, f.x, vi[kk]));
        }
    }
    __syncthreads();
#pragma unroll
    for (int kk = 0; kk < 8; kk++) {
        yr[kk * 256 + hf] = vr[kk];
        yi[kk * 256 + hf] = vi[kk];
    }
    __syncthreads();
    fft4_stages(yr, yi, xr, xi, tws, 8, tid, -1.0f);         // inverse (unnormalized)

    const float inv = 1.0f / 65536.0f;  // irfft_W * IFFT_H normalization (moved out of fp16 filt)
    for (int it = 0; it < 8; it++) {
        int idx = it * 256 + tid;
        int h = idx >> 3, c = idx & 7;
        base[(size_t)h * 129 * 8 + c] = make_float2(yr[c * 256 + h] * inv, yi[c * 256 + h] * inv);
    }
}

// ---------------- launch ----------------
extern "C" void kernel_launch(void* const* d_in, const int* in_sizes, int n_in,
                              void* d_out, int out_size) {
    const float* u    = (const float*)d_in[0];
    const float* kk   = (const float*)d_in[1];
    const float* gW[6];  for (int i = 0; i < 6; i++) gW[i]  = (const float*)d_in[2 + i];
    const float* dW[6];  for (int i = 0; i < 6; i++) dW[i]  = (const float*)d_in[8 + i];
    const float* frW[6]; for (int i = 0; i < 6; i++) frW[i] = (const float*)d_in[14 + i];
    const float* fiW[6]; for (int i = 0; i < 6; i++) fiW[i] = (const float*)d_in[20 + i];
    const float* bias = (const float*)d_in[26];
    float* out = (float*)d_out;

    k_mlp_gd<<<4096, 64>>>(kk,
        gW[0], gW[1], gW[2], gW[3], gW[4], gW[5],
        dW[0], dW[1], dW[2], dW[3], dW[4], dW[5]);
    k_filt<<<129, 256>>>(
        frW[0], frW[1], frW[2], frW[3], frW[4], frW[5],
        fiW[0], fiW[1], fiW[2], fiW[3], fiW[4], fiW[5]);

    k_row<0><<<NROW, 256>>>(u, nullptr, nullptr);
    for (int it = 0; it < 4; it++) {
        k_col<<<4 * 129, 256>>>();
        if (it < 3) {
            k_row<1><<<NROW, 256>>>(it == 0 ? u : nullptr, nullptr, nullptr);
        } else {
            k_row<2><<<NROW, 256>>>(nullptr, bias, out);
        }
    }
}

// round 6
// speedup vs baseline: 1.6559x; 1.1781x over previous
#include <cuda_runtime.h>
#include <cuda_fp16.h>
#include <cstddef>
#include <math.h>

// Problem constants: N=4, H=W=256, C=8, CK=2, ITER=4, HID=16, C2=64.
#define NROW 1024            // n*256+h rows
#define TS 260               // padded per-transform smem stride (4c+h bank permutation)

// ---------------- device scratch (no allocations allowed) ----------------
// gmat/dmat: [row][j][w][p]  p=half2 pair over k  (1024*8*256*4 half2 = 33.5MB each)
__device__ __align__(16) __half2 d_gmat[8388608];
__device__ __align__(16) __half2 d_dmat[8388608];
// filt: [wf][hf][jk] half2(re,im)  (129*256*64) 8.45MB
__device__ __align__(16) __half2 d_filt[129 * 256 * 64];
__device__ __align__(16) float2 d_uf[(size_t)1024 * 129 * 8]; // [row][wf][c]
__device__ __align__(16) float  d_u[(size_t)1024 * 256 * 8];  // iterated field

__device__ __forceinline__ __half2 u2h(unsigned u) {
    __half2 h; *reinterpret_cast<unsigned*>(&h) = u; return h;
}
__device__ __forceinline__ unsigned h2u(__half2 h) {
    return *reinterpret_cast<unsigned*>(&h);
}

// ---------------- helpers ----------------
__device__ __forceinline__ float gelu_t(float x) {
    float inner = 0.7978845608028654f * (x + 0.044715f * x * x * x);
    return 0.5f * x * (1.0f + tanhf(inner));
}

// MLP weights packed: w1[32]@0, b1[16]@32, w2[256]@48, b2[16]@304, w3[1024]@320, b3[64]@1344
__device__ __forceinline__ void load_mlp_w(float* dst,
    const float* w1, const float* b1, const float* w2, const float* b2,
    const float* w3, const float* b3, int tid, int nthr) {
    for (int i = tid; i < 32;   i += nthr) dst[i]        = w1[i];
    for (int i = tid; i < 16;   i += nthr) dst[32 + i]   = b1[i];
    for (int i = tid; i < 256;  i += nthr) dst[48 + i]   = w2[i];
    for (int i = tid; i < 16;   i += nthr) dst[304 + i]  = b2[i];
    for (int i = tid; i < 1024; i += nthr) dst[320 + i]  = w3[i];
    for (int i = tid; i < 64;   i += nthr) dst[1344 + i] = b3[i];
}

__device__ __forceinline__ void mlp2_h2(const float* __restrict__ Wm, float x0, float x1, float* h2) {
    float h1[16];
#pragma unroll
    for (int o = 0; o < 16; o++)
        h1[o] = gelu_t(fmaf(x0, Wm[o], fmaf(x1, Wm[16 + o], Wm[32 + o])));
#pragma unroll
    for (int o = 0; o < 16; o++) {
        float a = Wm[304 + o];
#pragma unroll
        for (int i = 0; i < 16; i++) a = fmaf(h1[i], Wm[48 + i * 16 + o], a);
        h2[o] = gelu_t(a);
    }
}

// In-smem Stockham radix-4 FFT, length 256, nf transforms at stride TS.
// tw[t] = exp(-2*pi*i*t/256). sign=+1 forward, sign=-1 unnormalized inverse.
// blockDim.x == 256; caller syncs before. Result ends in xr/xi.
__device__ __forceinline__ void fft4_stages(float* xr, float* xi, float* yr, float* yi,
                                            const float2* __restrict__ tw,
                                            int nf, int tid, float sign) {
    float *ar = xr, *ai = xi, *br = yr, *bi = yi;
#pragma unroll
    for (int s = 0; s < 4; s++) {
        int m = 1 << (2 * s);            // 1,4,16,64
        for (int t0 = tid; t0 < nf * 64; t0 += 256) {
            int base = (t0 >> 6) * TS;
            int t = t0 & 63;
            int jm = t & ~(m - 1);
            int r  = t & (m - 1);
            float2 w1v = tw[jm];
            float2 w2v = tw[2 * jm];
            float w1r = w1v.x, w1i = sign * w1v.y;
            float w2r = w2v.x, w2i = sign * w2v.y;

            float Ar = ar[base + t],       Ai = ai[base + t];
            float Br = ar[base + t + 64],  Bi = ai[base + t + 64];
            float Cr = ar[base + t + 128], Ci = ai[base + t + 128];
            float Dr = ar[base + t + 192], Di = ai[base + t + 192];

            float s0r = Ar + Cr, s0i = Ai + Ci;
            float d0r = Ar - Cr, d0i = Ai - Ci;
            float s2r = Br + Dr, s2i = Bi + Di;
            float d1r = Br - Dr, d1i = Bi - Di;
            float s1r = w1r * d0r - w1i * d0i;
            float s1i = w1r * d0i + w1i * d0r;
            float er = sign * d1i, ei = -sign * d1r;
            float s3r = w1r * er - w1i * ei;
            float s3i = w1r * ei + w1i * er;

            int o = base + 4 * jm + r;
            br[o]     = s0r + s2r;  bi[o]     = s0i + s2i;
            br[o + m] = s1r + s3r;  bi[o + m] = s1i + s3i;
            float u0r = s0r - s2r, u0i = s0i - s2i;
            br[o + 2 * m] = w2r * u0r - w2i * u0i;
            bi[o + 2 * m] = w2r * u0i + w2i * u0r;
            float u1r = s1r - s3r, u1i = s1i - s3i;
            br[o + 3 * m] = w2r * u1r - w2i * u1i;
            bi[o + 3 * m] = w2r * u1i + w2i * u1r;
        }
        __syncthreads();
        float* tp;
        tp = ar; ar = br; br = tp;
        tp = ai; ai = bi; bi = tp;
    }
}

__device__ __forceinline__ void fill_tw(float2* tws, int tid, int nthr) {
    for (int t = tid; t < 128; t += nthr) {
        float s, c;
        sincospif((float)t * (1.0f / 128.0f), &s, &c);
        tws[t] = make_float2(c, -s);
    }
}

// ---------------- kernel A: gamma/delta per-pixel 8x8 matrices (fp16, vectorized) ----
__global__ __launch_bounds__(256) void k_mlp_gd(const float* __restrict__ kin,
    const float* gw1, const float* gb1, const float* gw2, const float* gb2,
    const float* gw3, const float* gb3,
    const float* dw1, const float* db1, const float* dw2, const float* db2,
    const float* dw3, const float* db3) {
    __shared__ float Wg[1408], Wd[1408];
    int tid = threadIdx.x;
    load_mlp_w(Wg, gw1, gb1, gw2, gb2, gw3, gb3, tid, 256);
    load_mlp_w(Wd, dw1, db1, dw2, db2, dw3, db3, tid, 256);
    __syncthreads();

    int row = blockIdx.x;       // n*256 + h
    int w   = tid;
    int pix = row * 256 + w;
    float x0 = kin[pix * 2 + 0];
    float x1 = kin[pix * 2 + 1];

    float h2[16];
    const float inv64 = 1.0f / 64.0f;

    // gamma
    mlp2_h2(Wg, x0, x1, h2);
#pragma unroll
    for (int j = 0; j < 8; j++) {
        uint4 pk;
        unsigned* pku = &pk.x;
#pragma unroll
        for (int p = 0; p < 4; p++) {
            int jk0 = j * 8 + 2 * p;
            float v0 = Wg[1344 + jk0], v1 = Wg[1344 + jk0 + 1];
#pragma unroll
            for (int i = 0; i < 16; i++) {
                v0 = fmaf(h2[i], Wg[320 + i * 64 + jk0], v0);
                v1 = fmaf(h2[i], Wg[320 + i * 64 + jk0 + 1], v1);
            }
            pku[p] = h2u(__floats2half2_rn(v0 * inv64, v1 * inv64));
        }
        *reinterpret_cast<uint4*>(d_gmat + ((size_t)(row * 8 + j) * 256 + w) * 4) = pk;
    }
    // delta
    mlp2_h2(Wd, x0, x1, h2);
#pragma unroll
    for (int j = 0; j < 8; j++) {
        uint4 pk;
        unsigned* pku = &pk.x;
#pragma unroll
        for (int p = 0; p < 4; p++) {
            int jk0 = j * 8 + 2 * p;
            float v0 = Wd[1344 + jk0], v1 = Wd[1344 + jk0 + 1];
#pragma unroll
            for (int i = 0; i < 16; i++) {
                v0 = fmaf(h2[i], Wd[320 + i * 64 + jk0], v0);
                v1 = fmaf(h2[i], Wd[320 + i * 64 + jk0 + 1], v1);
            }
            pku[p] = h2u(__floats2half2_rn(v0 * inv64, v1 * inv64));
        }
        *reinterpret_cast<uint4*>(d_dmat + ((size_t)(row * 8 + j) * 256 + w) * 4) = pk;
    }
}

// ---------------- kernel B: spectral filter (fp16, [wf][hf][jk]) ----------------
// MLP input (kx, ky) = (wf, signed(hf)). Scale = 1/64 only; the 1/65536 FFT
// normalization is applied in k_col's store (fp16 would underflow).
__global__ __launch_bounds__(256) void k_filt(
    const float* rw1, const float* rb1, const float* rw2, const float* rb2,
    const float* rw3, const float* rb3,
    const float* iw1, const float* ib1, const float* iw2, const float* ib2,
    const float* iw3, const float* ib3) {
    __shared__ float Wr[1408], Wi[1408];
    int tid = threadIdx.x;
    load_mlp_w(Wr, rw1, rb1, rw2, rb2, rw3, rb3, tid, 256);
    load_mlp_w(Wi, iw1, ib1, iw2, ib2, iw3, ib3, tid, 256);
    __syncthreads();

    int wf = blockIdx.x;
    int hf = tid;
    float x0 = (float)wf;
    float x1 = (float)(hf < 128 ? hf : hf - 256);
    float h2r[16], h2i[16];
    mlp2_h2(Wr, x0, x1, h2r);
    mlp2_h2(Wi, x0, x1, h2i);
    const float sc = 1.0f / 64.0f;
    __half2* base = d_filt + ((size_t)wf * 256 + hf) * 64;
    for (int jk = 0; jk < 64; jk++) {
        float vr = Wr[1344 + jk], vi = Wi[1344 + jk];
#pragma unroll
        for (int i = 0; i < 16; i++) {
            vr = fmaf(h2r[i], Wr[320 + i * 64 + jk], vr);
            vi = fmaf(h2i[i], Wi[320 + i * 64 + jk], vi);
        }
        base[jk] = __floats2half2_rn(vr * sc, vi * sc);
    }
}

// ---------------- row pass ----------------
// MODE 0: du = u_in @ D, rfft_W -> Uf
// MODE 1: gu = irfft_W(Uf) ; u' = 2u + (gu-u)@G -> d_u ; du = u'@D ; rfft_W -> Uf
// MODE 2: gu = irfft_W(Uf) ; u' = 2u + (gu-u)@G ; out = gelu(u'+bias)
template <int MODE>
__global__ __launch_bounds__(256) void k_row(const float* __restrict__ uin,
                                             const float* __restrict__ bias,
                                             float* __restrict__ outp) {
    __shared__ float xr[4 * TS], xi[4 * TS], yr[4 * TS], yi[4 * TS];
    __shared__ float2 tws[128];

    int tid = threadIdx.x;
    int row = blockIdx.x;                       // n*256 + h
    fill_tw(tws, tid, 256);

    float2* ufrow = d_uf + (size_t)row * 129 * 8;
    const float* ubase = (uin != nullptr) ? uin : d_u;
    const float* urow  = ubase + (size_t)row * 2048;

    float unew[8];
    int w = tid;

    if (MODE == 0) {
        const float4* up = (const float4*)(urow + w * 8);
        float4 a = up[0], b = up[1];
        unew[0] = a.x; unew[1] = a.y; unew[2] = a.z; unew[3] = a.w;
        unew[4] = b.x; unew[5] = b.y; unew[6] = b.z; unew[7] = b.w;
    } else {
        // direct coalesced load of this thread's spectrum column (64B);
        // drop Im at DC/Nyquist (c2r semantics); Hermitian pack into xr/xi.
        int wfL = (tid <= 128) ? tid : 256 - tid;
        const float4* up = (const float4*)(ufrow + wfL * 8);
        float4 q0 = up[0], q1 = up[1], q2 = up[2], q3 = up[3];
        if (wfL == 0 || wfL == 128) {
            q0.y = 0.0f; q0.w = 0.0f; q1.y = 0.0f; q1.w = 0.0f;
            q2.y = 0.0f; q2.w = 0.0f; q3.y = 0.0f; q3.w = 0.0f;
        }
        float4 qs[4] = {q0, q1, q2, q3};
        if (tid <= 128) {
#pragma unroll
            for (int p = 0; p < 4; p++) {
                xr[p * TS + tid] = qs[p].x - qs[p].w;   // A.x - B.y
                xi[p * TS + tid] = qs[p].y + qs[p].z;   // A.y + B.x
            }
        } else {
#pragma unroll
            for (int p = 0; p < 4; p++) {
                xr[p * TS + tid] = qs[p].x + qs[p].w;   // A.x + B.y
                xi[p * TS + tid] = qs[p].z - qs[p].y;   // B.x - A.y
            }
        }
        __syncthreads();
        fft4_stages(xr, xi, yr, yi, tws, 4, tid, -1.0f);   // inverse (unnormalized)

        float gu[8], uu[8];
#pragma unroll
        for (int p = 0; p < 4; p++) {
            gu[2 * p]     = xr[p * TS + w];
            gu[2 * p + 1] = xi[p * TS + w];
        }
        {
            const float4* upu = (const float4*)(urow + w * 8);
            float4 a = upu[0], b = upu[1];
            uu[0] = a.x; uu[1] = a.y; uu[2] = a.z; uu[3] = a.w;
            uu[4] = b.x; uu[5] = b.y; uu[6] = b.z; uu[7] = b.w;
        }
        float tv[8];
#pragma unroll
        for (int j = 0; j < 8; j++) tv[j] = gu[j] - uu[j];
#pragma unroll
        for (int kk = 0; kk < 8; kk++) unew[kk] = 2.0f * uu[kk];
        const __half2* G = d_gmat + (size_t)row * 8 * 1024 + w * 4;
#pragma unroll
        for (int j = 0; j < 8; j++) {
            float tj = tv[j];
            uint4 raw = *reinterpret_cast<const uint4*>(G + j * 1024);
            float2 g0 = __half22float2(u2h(raw.x));
            float2 g1 = __half22float2(u2h(raw.y));
            float2 g2 = __half22float2(u2h(raw.z));
            float2 g3 = __half22float2(u2h(raw.w));
            unew[0] = fmaf(tj, g0.x, unew[0]); unew[1] = fmaf(tj, g0.y, unew[1]);
            unew[2] = fmaf(tj, g1.x, unew[2]); unew[3] = fmaf(tj, g1.y, unew[3]);
            unew[4] = fmaf(tj, g2.x, unew[4]); unew[5] = fmaf(tj, g2.y, unew[5]);
            unew[6] = fmaf(tj, g3.x, unew[6]); unew[7] = fmaf(tj, g3.y, unew[7]);
        }
        if (MODE == 2) {
            float4 o0, o1;
            o0.x = gelu_t(unew[0] + bias[0]);
            o0.y = gelu_t(unew[1] + bias[1]);
            o0.z = gelu_t(unew[2] + bias[2]);
            o0.w = gelu_t(unew[3] + bias[3]);
            o1.x = gelu_t(unew[4] + bias[4]);
            o1.y = gelu_t(unew[5] + bias[5]);
            o1.z = gelu_t(unew[6] + bias[6]);
            o1.w = gelu_t(unew[7] + bias[7]);
            float4* op = (float4*)(outp + (size_t)row * 2048 + w * 8);
            op[0] = o0; op[1] = o1;
            return;
        }
        // MODE 1: persist u'
        {
            float4 o0, o1;
            o0.x = unew[0]; o0.y = unew[1]; o0.z = unew[2]; o0.w = unew[3];
            o1.x = unew[4]; o1.y = unew[5]; o1.z = unew[6]; o1.w = unew[7];
            float4* op = (float4*)(d_u + (size_t)row * 2048 + w * 8);
            op[0] = o0; op[1] = o1;
        }
    }

    // du = unew @ D ; pack ; forward FFT ; unpack rfft ; write Uf
    {
        const __half2* D = d_dmat + (size_t)row * 8 * 1024 + w * 4;
        float du[8];
#pragma unroll
        for (int kk = 0; kk < 8; kk++) du[kk] = 0.0f;
#pragma unroll
        for (int j = 0; j < 8; j++) {
            float uj = unew[j];
            uint4 raw = *reinterpret_cast<const uint4*>(D + j * 1024);
            float2 g0 = __half22float2(u2h(raw.x));
            float2 g1 = __half22float2(u2h(raw.y));
            float2 g2 = __half22float2(u2h(raw.z));
            float2 g3 = __half22float2(u2h(raw.w));
            du[0] = fmaf(uj, g0.x, du[0]); du[1] = fmaf(uj, g0.y, du[1]);
            du[2] = fmaf(uj, g1.x, du[2]); du[3] = fmaf(uj, g1.y, du[3]);
            du[4] = fmaf(uj, g2.x, du[4]); du[5] = fmaf(uj, g2.y, du[5]);
            du[6] = fmaf(uj, g3.x, du[6]); du[7] = fmaf(uj, g3.y, du[7]);
        }
        if (MODE != 0) __syncthreads();   // all gu reads of xr/xi complete
#pragma unroll
        for (int p = 0; p < 4; p++) {
            xr[p * TS + w] = du[2 * p];
            xi[p * TS + w] = du[2 * p + 1];
        }
        __syncthreads();
        fft4_stages(xr, xi, yr, yi, tws, 4, tid, 1.0f);    // forward
        if (tid <= 128) {
            int k2 = tid, m2 = (256 - k2) & 255;
#pragma unroll
            for (int p = 0; p < 4; p++) {
                float Zr = xr[p * TS + k2], Zi = xi[p * TS + k2];
                float Qr = xr[p * TS + m2], Qi = xi[p * TS + m2];
                float2 A = make_float2(0.5f * (Zr + Qr), 0.5f * (Zi - Qi));
                float2 B = make_float2(0.5f * (Zi + Qi), 0.5f * (Qr - Zr));
                ufrow[k2 * 8 + 2 * p]     = A;
                ufrow[k2 * 8 + 2 * p + 1] = B;
            }
        }
    }
}

// ---------------- column pass: FFT_H, filter matvec, IFFT_H (in-place on Uf) ---------
__global__ __launch_bounds__(256) void k_col() {
    __shared__ float xr[8 * TS], xi[8 * TS], yr[8 * TS], yi[8 * TS];
    __shared__ float2 tws[128];
    int tid = threadIdx.x;
    int wf = blockIdx.x % 129;
    int n  = blockIdx.x / 129;
    fill_tw(tws, tid, 256);

    float2* base = d_uf + ((size_t)n * 256 * 129 + wf) * 8;  // + h*129*8 + c
    for (int it = 0; it < 8; it++) {
        int idx = it * 256 + tid;
        int h = idx >> 3, c = idx & 7;
        float2 v = base[(size_t)h * 129 * 8 + c];
        xr[c * TS + h] = v.x;
        xi[c * TS + h] = v.y;
    }
    __syncthreads();
    fft4_stages(xr, xi, yr, yi, tws, 8, tid, 1.0f);          // forward along H

    int hf = tid;
    float vr[8], vi[8];
#pragma unroll
    for (int kk = 0; kk < 8; kk++) { vr[kk] = 0.0f; vi[kk] = 0.0f; }
    const __half2* F = d_filt + ((size_t)wf * 256 + hf) * 64;
#pragma unroll
    for (int j = 0; j < 8; j++) {
        float zr = xr[j * TS + hf], zi = xi[j * TS + hf];
        uint4 fa = *reinterpret_cast<const uint4*>(F + j * 8);
        uint4 fb = *reinterpret_cast<const uint4*>(F + j * 8 + 4);
        const unsigned* fu[2] = {&fa.x, &fb.x};
#pragma unroll
        for (int half = 0; half < 2; half++) {
#pragma unroll
            for (int q = 0; q < 4; q++) {
                int kk = half * 4 + q;
                float2 f = __half22float2(u2h(fu[half][q]));
                vr[kk] = fmaf(zr, f.x, fmaf(-zi, f.y, vr[kk]));
                vi[kk] = fmaf(zr, f.y, fmaf(zi, f.x, vi[kk]));
            }
        }
    }
#pragma unroll
    for (int kk = 0; kk < 8; kk++) {
        yr[kk * TS + hf] = vr[kk];
        yi[kk * TS + hf] = vi[kk];
    }
    __syncthreads();
    fft4_stages(yr, yi, xr, xi, tws, 8, tid, -1.0f);         // inverse (unnormalized)

    const float inv = 1.0f / 65536.0f;  // both inverse-FFT norms (kept out of fp16 filt)
    for (int it = 0; it < 8; it++) {
        int idx = it * 256 + tid;
        int h = idx >> 3, c = idx & 7;
        base[(size_t)h * 129 * 8 + c] = make_float2(yr[c * TS + h] * inv, yi[c * TS + h] * inv);
    }
}

// ---------------- launch ----------------
extern "C" void kernel_launch(void* const* d_in, const int* in_sizes, int n_in,
                              void* d_out, int out_size) {
    const float* u    = (const float*)d_in[0];
    const float* kk   = (const float*)d_in[1];
    const float* gW[6];  for (int i = 0; i < 6; i++) gW[i]  = (const float*)d_in[2 + i];
    const float* dW[6];  for (int i = 0; i < 6; i++) dW[i]  = (const float*)d_in[8 + i];
    const float* frW[6]; for (int i = 0; i < 6; i++) frW[i] = (const float*)d_in[14 + i];
    const float* fiW[6]; for (int i = 0; i < 6; i++) fiW[i] = (const float*)d_in[20 + i];
    const float* bias = (const float*)d_in[26];
    float* out = (float*)d_out;

    k_mlp_gd<<<1024, 256>>>(kk,
        gW[0], gW[1], gW[2], gW[3], gW[4], gW[5],
        dW[0], dW[1], dW[2], dW[3], dW[4], dW[5]);
    k_filt<<<129, 256>>>(
        frW[0], frW[1], frW[2], frW[3], frW[4], frW[5],
        fiW[0], fiW[1], fiW[2], fiW[3], fiW[4], fiW[5]);

    k_row<0><<<NROW, 256>>>(u, nullptr, nullptr);
    for (int it = 0; it < 4; it++) {
        k_col<<<4 * 129, 256>>>();
        if (it < 3) {
            k_row<1><<<NROW, 256>>>(it == 0 ? u : nullptr, nullptr, nullptr);
        } else {
            k_row<2><<<NROW, 256>>>(nullptr, bias, out);
        }
    }
}

// round 7
// speedup vs baseline: 1.8939x; 1.1437x over previous
#include <cuda_runtime.h>
#include <cuda_fp16.h>
#include <cstddef>
#include <math.h>

// Problem constants: N=4, H=W=256, C=8, CK=2, ITER=4, HID=16, C2=64.
#define NROW 1024            // n*256+h rows
#define TS 260               // per-transform smem stride (floats)

// Bank-conflict-free smem permutation for the radix-4 Stockham access sets.
// P(i) = i ^ ((i>>2)&28): bits 2..4 ^= bits 4..6. Invertible; preserves
// aligned 4-blocks (float4 stores stay legal). Verified conflict-free for:
// reads {t+64q}, writes at m=1 (as float4), m=4, m=16, m=64, and all
// contiguous-lane pack/unpack/transpose patterns with stride 260.
__device__ __forceinline__ int PSW(int i) { return i ^ ((i >> 2) & 28); }

// ---------------- device scratch (no allocations allowed) ----------------
// gmat/dmat: [row][j][w][p]  p=half2 pair over k  (1024*8*256*4 half2 = 33.5MB each)
__device__ __align__(16) __half2 d_gmat[8388608];
__device__ __align__(16) __half2 d_dmat[8388608];
// filt: [wf][g][j][hf][q]  g=kk-half, q=0..3 -> kk=4g+q   (129*2*8*256*4 half2 = 8.45MB)
__device__ __align__(16) __half2 d_filt[(size_t)129 * 2 * 8 * 256 * 4];
__device__ __align__(16) float2 d_uf[(size_t)1024 * 129 * 8]; // [row][wf][c]
__device__ __align__(16) float  d_u[(size_t)1024 * 256 * 8];  // iterated field

__device__ __forceinline__ __half2 u2h(unsigned u) {
    __half2 h; *reinterpret_cast<unsigned*>(&h) = u; return h;
}
__device__ __forceinline__ unsigned h2u(__half2 h) {
    return *reinterpret_cast<unsigned*>(&h);
}

// ---------------- helpers ----------------
__device__ __forceinline__ float gelu_t(float x) {
    float inner = 0.7978845608028654f * (x + 0.044715f * x * x * x);
    return 0.5f * x * (1.0f + tanhf(inner));
}

// MLP weights packed: w1[32]@0, b1[16]@32, w2[256]@48, b2[16]@304, w3[1024]@320, b3[64]@1344
__device__ __forceinline__ void load_mlp_w(float* dst,
    const float* w1, const float* b1, const float* w2, const float* b2,
    const float* w3, const float* b3, int tid, int nthr) {
    for (int i = tid; i < 32;   i += nthr) dst[i]        = w1[i];
    for (int i = tid; i < 16;   i += nthr) dst[32 + i]   = b1[i];
    for (int i = tid; i < 256;  i += nthr) dst[48 + i]   = w2[i];
    for (int i = tid; i < 16;   i += nthr) dst[304 + i]  = b2[i];
    for (int i = tid; i < 1024; i += nthr) dst[320 + i]  = w3[i];
    for (int i = tid; i < 64;   i += nthr) dst[1344 + i] = b3[i];
}

__device__ __forceinline__ void mlp2_h2(const float* __restrict__ Wm, float x0, float x1, float* h2) {
    float h1[16];
#pragma unroll
    for (int o = 0; o < 16; o++)
        h1[o] = gelu_t(fmaf(x0, Wm[o], fmaf(x1, Wm[16 + o], Wm[32 + o])));
#pragma unroll
    for (int o = 0; o < 16; o++) {
        float a = Wm[304 + o];
#pragma unroll
        for (int i = 0; i < 16; i++) a = fmaf(h1[i], Wm[48 + i * 16 + o], a);
        h2[o] = gelu_t(a);
    }
}

// In-smem Stockham radix-4 FFT, length 256, nf transforms at stride TS,
// all smem indices permuted by PSW (conflict-free). NT = threads cooperating.
// tw[t] = exp(-2*pi*i*t/256). sign=+1 forward, sign=-1 unnormalized inverse.
// Caller syncs before. Result ends in xr/xi (4 swaps).
template <int NT>
__device__ __forceinline__ void fft4_stages(float* xr, float* xi, float* yr, float* yi,
                                            const float2* __restrict__ tw,
                                            int nf, int tid, float sign) {
    float *ar = xr, *ai = xi, *br = yr, *bi = yi;
#pragma unroll
    for (int s = 0; s < 4; s++) {
        int m = 1 << (2 * s);            // 1,4,16,64
        for (int t0 = tid; t0 < nf * 64; t0 += NT) {
            int base = (t0 >> 6) * TS;
            int t = t0 & 63;
            int jm = t & ~(m - 1);
            int r  = t & (m - 1);
            float2 w1v = tw[jm];
            float2 w2v = tw[2 * jm];
            float w1r = w1v.x, w1i = sign * w1v.y;
            float w2r = w2v.x, w2i = sign * w2v.y;

            float Ar = ar[base + PSW(t)],       Ai = ai[base + PSW(t)];
            float Br = ar[base + PSW(t + 64)],  Bi = ai[base + PSW(t + 64)];
            float Cr = ar[base + PSW(t + 128)], Ci = ai[base + PSW(t + 128)];
            float Dr = ar[base + PSW(t + 192)], Di = ai[base + PSW(t + 192)];

            float s0r = Ar + Cr, s0i = Ai + Ci;
            float d0r = Ar - Cr, d0i = Ai - Ci;
            float s2r = Br + Dr, s2i = Bi + Di;
            float d1r = Br - Dr, d1i = Bi - Di;
            float s1r = w1r * d0r - w1i * d0i;
            float s1i = w1r * d0i + w1i * d0r;
            float er = sign * d1i, ei = -sign * d1r;
            float s3r = w1r * er - w1i * ei;
            float s3i = w1r * ei + w1i * er;

            float u0r = s0r - s2r, u0i = s0i - s2i;
            float u1r = s1r - s3r, u1i = s1i - s3i;
            float o2r = w2r * u0r - w2i * u0i;
            float o2i = w2r * u0i + w2i * u0r;
            float o3r = w2r * u1r - w2i * u1i;
            float o3i = w2r * u1i + w2i * u1r;

            if (s == 0) {
                // m=1: contiguous outputs -> one float4 store per array
                int o = base + PSW(4 * t);
                *reinterpret_cast<float4*>(br + o) =
                    make_float4(s0r + s2r, s1r + s3r, o2r, o3r);
                *reinterpret_cast<float4*>(bi + o) =
                    make_float4(s0i + s2i, s1i + s3i, o2i, o3i);
            } else {
                int o = 4 * jm + r;
                br[base + PSW(o)]         = s0r + s2r;
                bi[base + PSW(o)]         = s0i + s2i;
                br[base + PSW(o + m)]     = s1r + s3r;
                bi[base + PSW(o + m)]     = s1i + s3i;
                br[base + PSW(o + 2 * m)] = o2r;
                bi[base + PSW(o + 2 * m)] = o2i;
                br[base + PSW(o + 3 * m)] = o3r;
                bi[base + PSW(o + 3 * m)] = o3i;
            }
        }
        __syncthreads();
        float* tp;
        tp = ar; ar = br; br = tp;
        tp = ai; ai = bi; bi = tp;
    }
}

__device__ __forceinline__ void fill_tw(float2* tws, int tid, int nthr) {
    for (int t = tid; t < 128; t += nthr) {
        float s, c;
        sincospif((float)t * (1.0f / 128.0f), &s, &c);
        tws[t] = make_float2(c, -s);
    }
}

// ---------------- kernel A: gamma/delta per-pixel 8x8 matrices (fp16, vectorized) ----
__global__ __launch_bounds__(256) void k_mlp_gd(const float* __restrict__ kin,
    const float* gw1, const float* gb1, const float* gw2, const float* gb2,
    const float* gw3, const float* gb3,
    const float* dw1, const float* db1, const float* dw2, const float* db2,
    const float* dw3, const float* db3) {
    __shared__ float Wg[1408], Wd[1408];
    int tid = threadIdx.x;
    load_mlp_w(Wg, gw1, gb1, gw2, gb2, gw3, gb3, tid, 256);
    load_mlp_w(Wd, dw1, db1, dw2, db2, dw3, db3, tid, 256);
    __syncthreads();

    int row = blockIdx.x;       // n*256 + h
    int w   = tid;
    int pix = row * 256 + w;
    float x0 = kin[pix * 2 + 0];
    float x1 = kin[pix * 2 + 1];

    float h2[16];
    const float inv64 = 1.0f / 64.0f;

    // gamma
    mlp2_h2(Wg, x0, x1, h2);
#pragma unroll
    for (int j = 0; j < 8; j++) {
        uint4 pk;
        unsigned* pku = &pk.x;
#pragma unroll
        for (int p = 0; p < 4; p++) {
            int jk0 = j * 8 + 2 * p;
            float v0 = Wg[1344 + jk0], v1 = Wg[1344 + jk0 + 1];
#pragma unroll
            for (int i = 0; i < 16; i++) {
                v0 = fmaf(h2[i], Wg[320 + i * 64 + jk0], v0);
                v1 = fmaf(h2[i], Wg[320 + i * 64 + jk0 + 1], v1);
            }
            pku[p] = h2u(__floats2half2_rn(v0 * inv64, v1 * inv64));
        }
        *reinterpret_cast<uint4*>(d_gmat + ((size_t)(row * 8 + j) * 256 + w) * 4) = pk;
    }
    // delta
    mlp2_h2(Wd, x0, x1, h2);
#pragma unroll
    for (int j = 0; j < 8; j++) {
        uint4 pk;
        unsigned* pku = &pk.x;
#pragma unroll
        for (int p = 0; p < 4; p++) {
            int jk0 = j * 8 + 2 * p;
            float v0 = Wd[1344 + jk0], v1 = Wd[1344 + jk0 + 1];
#pragma unroll
            for (int i = 0; i < 16; i++) {
                v0 = fmaf(h2[i], Wd[320 + i * 64 + jk0], v0);
                v1 = fmaf(h2[i], Wd[320 + i * 64 + jk0 + 1], v1);
            }
            pku[p] = h2u(__floats2half2_rn(v0 * inv64, v1 * inv64));
        }
        *reinterpret_cast<uint4*>(d_dmat + ((size_t)(row * 8 + j) * 256 + w) * 4) = pk;
    }
}

// ---------------- kernel B: spectral filter (fp16, [wf][g][j][hf][q]) --------------
// MLP input (kx, ky) = (wf, signed(hf)). Scale = 1/64 only; the 1/65536 FFT
// normalization is applied in k_col's store (fp16 would underflow).
__global__ __launch_bounds__(256) void k_filt(
    const float* rw1, const float* rb1, const float* rw2, const float* rb2,
    const float* rw3, const float* rb3,
    const float* iw1, const float* ib1, const float* iw2, const float* ib2,
    const float* iw3, const float* ib3) {
    __shared__ float Wr[1408], Wi[1408];
    int tid = threadIdx.x;
    load_mlp_w(Wr, rw1, rb1, rw2, rb2, rw3, rb3, tid, 256);
    load_mlp_w(Wi, iw1, ib1, iw2, ib2, iw3, ib3, tid, 256);
    __syncthreads();

    int wf = blockIdx.x;
    int hf = tid;
    float x0 = (float)wf;
    float x1 = (float)(hf < 128 ? hf : hf - 256);
    float h2r[16], h2i[16];
    mlp2_h2(Wr, x0, x1, h2r);
    mlp2_h2(Wi, x0, x1, h2i);
    const float sc = 1.0f / 64.0f;
#pragma unroll
    for (int g = 0; g < 2; g++) {
#pragma unroll
        for (int j = 0; j < 8; j++) {
            uint4 pk;
            unsigned* pku = &pk.x;
#pragma unroll
            for (int q = 0; q < 4; q++) {
                int jk = j * 8 + 4 * g + q;
                float vr = Wr[1344 + jk], vi = Wi[1344 + jk];
#pragma unroll
                for (int i = 0; i < 16; i++) {
                    vr = fmaf(h2r[i], Wr[320 + i * 64 + jk], vr);
                    vi = fmaf(h2i[i], Wi[320 + i * 64 + jk], vi);
                }
                pku[q] = h2u(__floats2half2_rn(vr * sc, vi * sc));
            }
            size_t idx = ((((size_t)wf * 2 + g) * 8 + j) * 256 + hf) * 4;
            *reinterpret_cast<uint4*>(d_filt + idx) = pk;
        }
    }
}

// ---------------- row pass ----------------
// MODE 0: du = u_in @ D, rfft_W -> Uf
// MODE 1: gu = irfft_W(Uf) ; u' = 2u + (gu-u)@G -> d_u ; du = u'@D ; rfft_W -> Uf
// MODE 2: gu = irfft_W(Uf) ; u' = 2u + (gu-u)@G ; out = gelu(u'+bias)
template <int MODE>
__global__ __launch_bounds__(256) void k_row(const float* __restrict__ uin,
                                             const float* __restrict__ bias,
                                             float* __restrict__ outp) {
    __shared__ __align__(16) float xr[4 * TS], xi[4 * TS], yr[4 * TS], yi[4 * TS];
    __shared__ float2 tws[128];

    int tid = threadIdx.x;
    int row = blockIdx.x;                       // n*256 + h
    fill_tw(tws, tid, 256);

    float2* ufrow = d_uf + (size_t)row * 129 * 8;
    const float* ubase = (uin != nullptr) ? uin : d_u;
    const float* urow  = ubase + (size_t)row * 2048;

    float unew[8];
    int w = tid;

    if (MODE == 0) {
        const float4* up = (const float4*)(urow + w * 8);
        float4 a = up[0], b = up[1];
        unew[0] = a.x; unew[1] = a.y; unew[2] = a.z; unew[3] = a.w;
        unew[4] = b.x; unew[5] = b.y; unew[6] = b.z; unew[7] = b.w;
    } else {
        // direct coalesced load of this thread's spectrum column (64B);
        // drop Im at DC/Nyquist (c2r semantics); Hermitian pack into xr/xi.
        int wfL = (tid <= 128) ? tid : 256 - tid;
        const float4* up = (const float4*)(ufrow + wfL * 8);
        float4 q0 = up[0], q1 = up[1], q2 = up[2], q3 = up[3];
        if (wfL == 0 || wfL == 128) {
            q0.y = 0.0f; q0.w = 0.0f; q1.y = 0.0f; q1.w = 0.0f;
            q2.y = 0.0f; q2.w = 0.0f; q3.y = 0.0f; q3.w = 0.0f;
        }
        float4 qs[4] = {q0, q1, q2, q3};
        int pt = PSW(tid);
        if (tid <= 128) {
#pragma unroll
            for (int p = 0; p < 4; p++) {
                xr[p * TS + pt] = qs[p].x - qs[p].w;   // A.x - B.y
                xi[p * TS + pt] = qs[p].y + qs[p].z;   // A.y + B.x
            }
        } else {
#pragma unroll
            for (int p = 0; p < 4; p++) {
                xr[p * TS + pt] = qs[p].x + qs[p].w;   // A.x + B.y
                xi[p * TS + pt] = qs[p].z - qs[p].y;   // B.x - A.y
            }
        }
        __syncthreads();
        fft4_stages<256>(xr, xi, yr, yi, tws, 4, tid, -1.0f);   // inverse (unnormalized)

        float gu[8], uu[8];
        int pw = PSW(w);
#pragma unroll
        for (int p = 0; p < 4; p++) {
            gu[2 * p]     = xr[p * TS + pw];
            gu[2 * p + 1] = xi[p * TS + pw];
        }
        {
            const float4* upu = (const float4*)(urow + w * 8);
            float4 a = upu[0], b = upu[1];
            uu[0] = a.x; uu[1] = a.y; uu[2] = a.z; uu[3] = a.w;
            uu[4] = b.x; uu[5] = b.y; uu[6] = b.z; uu[7] = b.w;
        }
        float tv[8];
#pragma unroll
        for (int j = 0; j < 8; j++) tv[j] = gu[j] - uu[j];
#pragma unroll
        for (int kk = 0; kk < 8; kk++) unew[kk] = 2.0f * uu[kk];
        const __half2* G = d_gmat + (size_t)row * 8 * 1024 + w * 4;
#pragma unroll
        for (int j = 0; j < 8; j++) {
            float tj = tv[j];
            uint4 raw = *reinterpret_cast<const uint4*>(G + j * 1024);
            float2 g0 = __half22float2(u2h(raw.x));
            float2 g1 = __half22float2(u2h(raw.y));
            float2 g2 = __half22float2(u2h(raw.z));
            float2 g3 = __half22float2(u2h(raw.w));
            unew[0] = fmaf(tj, g0.x, unew[0]); unew[1] = fmaf(tj, g0.y, unew[1]);
            unew[2] = fmaf(tj, g1.x, unew[2]); unew[3] = fmaf(tj, g1.y, unew[3]);
            unew[4] = fmaf(tj, g2.x, unew[4]); unew[5] = fmaf(tj, g2.y, unew[5]);
            unew[6] = fmaf(tj, g3.x, unew[6]); unew[7] = fmaf(tj, g3.y, unew[7]);
        }
        if (MODE == 2) {
            float4 o0, o1;
            o0.x = gelu_t(unew[0] + bias[0]);
            o0.y = gelu_t(unew[1] + bias[1]);
            o0.z = gelu_t(unew[2] + bias[2]);
            o0.w = gelu_t(unew[3] + bias[3]);
            o1.x = gelu_t(unew[4] + bias[4]);
            o1.y = gelu_t(unew[5] + bias[5]);
            o1.z = gelu_t(unew[6] + bias[6]);
            o1.w = gelu_t(unew[7] + bias[7]);
            float4* op = (float4*)(outp + (size_t)row * 2048 + w * 8);
            op[0] = o0; op[1] = o1;
            return;
        }
        // MODE 1: persist u'
        {
            float4 o0, o1;
            o0.x = unew[0]; o0.y = unew[1]; o0.z = unew[2]; o0.w = unew[3];
            o1.x = unew[4]; o1.y = unew[5]; o1.z = unew[6]; o1.w = unew[7];
            float4* op = (float4*)(d_u + (size_t)row * 2048 + w * 8);
            op[0] = o0; op[1] = o1;
        }
    }

    // du = unew @ D ; pack ; forward FFT ; unpack rfft ; write Uf
    {
        const __half2* D = d_dmat + (size_t)row * 8 * 1024 + w * 4;
        float du[8];
#pragma unroll
        for (int kk = 0; kk < 8; kk++) du[kk] = 0.0f;
#pragma unroll
        for (int j = 0; j < 8; j++) {
            float uj = unew[j];
            uint4 raw = *reinterpret_cast<const uint4*>(D + j * 1024);
            float2 g0 = __half22float2(u2h(raw.x));
            float2 g1 = __half22float2(u2h(raw.y));
            float2 g2 = __half22float2(u2h(raw.z));
            float2 g3 = __half22float2(u2h(raw.w));
            du[0] = fmaf(uj, g0.x, du[0]); du[1] = fmaf(uj, g0.y, du[1]);
            du[2] = fmaf(uj, g1.x, du[2]); du[3] = fmaf(uj, g1.y, du[3]);
            du[4] = fmaf(uj, g2.x, du[4]); du[5] = fmaf(uj, g2.y, du[5]);
            du[6] = fmaf(uj, g3.x, du[6]); du[7] = fmaf(uj, g3.y, du[7]);
        }
        if (MODE != 0) __syncthreads();   // all gu reads of xr/xi complete
        int pw = PSW(w);
#pragma unroll
        for (int p = 0; p < 4; p++) {
            xr[p * TS + pw] = du[2 * p];
            xi[p * TS + pw] = du[2 * p + 1];
        }
        __syncthreads();
        fft4_stages<256>(xr, xi, yr, yi, tws, 4, tid, 1.0f);    // forward
        if (tid <= 128) {
            int k2 = tid, m2 = (256 - k2) & 255;
            int pk2 = PSW(k2), pm2 = PSW(m2);
#pragma unroll
            for (int p = 0; p < 4; p++) {
                float Zr = xr[p * TS + pk2], Zi = xi[p * TS + pk2];
                float Qr = xr[p * TS + pm2], Qi = xi[p * TS + pm2];
                float2 A = make_float2(0.5f * (Zr + Qr), 0.5f * (Zi - Qi));
                float2 B = make_float2(0.5f * (Zi + Qi), 0.5f * (Qr - Zr));
                ufrow[k2 * 8 + 2 * p]     = A;
                ufrow[k2 * 8 + 2 * p + 1] = B;
            }
        }
    }
}

// ---------------- column pass: FFT_H, filter matvec, IFFT_H (in-place on Uf) ---------
// 512 threads: one butterfly per thread per stage; matvec split by kk-half.
__global__ __launch_bounds__(512) void k_col() {
    __shared__ __align__(16) float xr[8 * TS], xi[8 * TS], yr[8 * TS], yi[8 * TS];
    __shared__ float2 tws[128];
    int tid = threadIdx.x;
    int wf = blockIdx.x % 129;
    int n  = blockIdx.x / 129;
    fill_tw(tws, tid, 512);

    float2* base = d_uf + ((size_t)n * 256 * 129 + wf) * 8;  // + h*129*8 + c
    for (int it = 0; it < 4; it++) {
        int idx = it * 512 + tid;
        int h = idx >> 3, c = idx & 7;
        float2 v = base[(size_t)h * 129 * 8 + c];
        int a = c * TS + PSW(h);
        xr[a] = v.x;
        xi[a] = v.y;
    }
    __syncthreads();
    fft4_stages<512>(xr, xi, yr, yi, tws, 8, tid, 1.0f);     // forward along H

    int hf = tid & 255;
    int g  = tid >> 8;          // kk-half
    int ph = PSW(hf);
    float vr[4], vi[4];
#pragma unroll
    for (int q = 0; q < 4; q++) { vr[q] = 0.0f; vi[q] = 0.0f; }
    const __half2* F = d_filt + (((size_t)wf * 2 + g) * 8 * 256 + hf) * 4;
#pragma unroll
    for (int j = 0; j < 8; j++) {
        float zr = xr[j * TS + ph], zi = xi[j * TS + ph];
        uint4 fa = *reinterpret_cast<const uint4*>(F + (size_t)j * 1024);
        const unsigned* fu = &fa.x;
#pragma unroll
        for (int q = 0; q < 4; q++) {
            float2 f = __half22float2(u2h(fu[q]));
            vr[q] = fmaf(zr, f.x, fmaf(-zi, f.y, vr[q]));
            vi[q] = fmaf(zr, f.y, fmaf(zi, f.x, vi[q]));
        }
    }
    __syncthreads();
#pragma unroll
    for (int q = 0; q < 4; q++) {
        int kk = 4 * g + q;
        yr[kk * TS + ph] = vr[q];
        yi[kk * TS + ph] = vi[q];
    }
    __syncthreads();
    fft4_stages<512>(yr, yi, xr, xi, tws, 8, tid, -1.0f);    // inverse (unnormalized)

    const float inv = 1.0f / 65536.0f;  // both inverse-FFT norms (kept out of fp16 filt)
    for (int it = 0; it < 4; it++) {
        int idx = it * 512 + tid;
        int h = idx >> 3, c = idx & 7;
        int a = c * TS + PSW(h);
        base[(size_t)h * 129 * 8 + c] = make_float2(yr[a] * inv, yi[a] * inv);
    }
}

// ---------------- launch ----------------
extern "C" void kernel_launch(void* const* d_in, const int* in_sizes, int n_in,
                              void* d_out, int out_size) {
    const float* u    = (const float*)d_in[0];
    const float* kk   = (const float*)d_in[1];
    const float* gW[6];  for (int i = 0; i < 6; i++) gW[i]  = (const float*)d_in[2 + i];
    const float* dW[6];  for (int i = 0; i < 6; i++) dW[i]  = (const float*)d_in[8 + i];
    const float* frW[6]; for (int i = 0; i < 6; i++) frW[i] = (const float*)d_in[14 + i];
    const float* fiW[6]; for (int i = 0; i < 6; i++) fiW[i] = (const float*)d_in[20 + i];
    const float* bias = (const float*)d_in[26];
    float* out = (float*)d_out;

    k_mlp_gd<<<1024, 256>>>(kk,
        gW[0], gW[1], gW[2], gW[3], gW[4], gW[5],
        dW[0], dW[1], dW[2], dW[3], dW[4], dW[5]);
    k_filt<<<129, 256>>>(
        frW[0], frW[1], frW[2], frW[3], frW[4], frW[5],
        fiW[0], fiW[1], fiW[2], fiW[3], fiW[4], fiW[5]);

    k_row<0><<<NROW, 256>>>(u, nullptr, nullptr);
    for (int it = 0; it < 4; it++) {
        k_col<<<4 * 129, 512>>>();
        if (it < 3) {
            k_row<1><<<NROW, 256>>>(it == 0 ? u : nullptr, nullptr, nullptr);
        } else {
            k_row<2><<<NROW, 256>>>(nullptr, bias, out);
        }
    }
}